// round 1
// baseline (speedup 1.0000x reference)
#include <cuda_runtime.h>
#include <cstddef>

// ---------------------------------------------------------------------------
// Problem constants (fixed by the dataset)
// ---------------------------------------------------------------------------
#define NTYPES 6
#define HID    256
#define DIN    192   // DV + C
#define DV     128
#define CCH    64
#define IMH    192
#define IMW    192
#define GARM   24
#define NV_TOT 103104  // sum over garments of vnums = 4 * (4248+4258+5327+3721+5404+2818)

// Static device scratch (allocation-free rule: __device__ globals are allowed)
__device__ float g_garf[GARM * CCH];
__device__ float g_h1[(size_t)NV_TOT * HID];
__device__ float g_h2[(size_t)NV_TOT * HID];

struct P {
    const int* idx[NTYPES];
    int M[NTYPES];
    int rowOff[NTYPES + 1];   // cumsum of M (type-ordered global rows)
    int tileOff[NTYPES + 1];  // cumsum of ceil(M/128)
};

// ---------------------------------------------------------------------------
// Packed f32x2 helpers (FFMA2: 2x fp32 FMA rate on sm_103a, PTX-only)
// ---------------------------------------------------------------------------
__device__ __forceinline__ unsigned long long pk2(float x, float y) {
    unsigned long long r;
    asm("mov.b64 %0, {%1, %2};" : "=l"(r) : "f"(x), "f"(y));
    return r;
}
__device__ __forceinline__ void fma2(unsigned long long& d, unsigned long long a, unsigned long long b) {
    asm("fma.rn.f32x2 %0, %1, %2, %0;" : "+l"(d) : "l"(a), "l"(b));
}
__device__ __forceinline__ float2 upk2(unsigned long long v) {
    float2 r;
    asm("mov.b64 {%0, %1}, %2;" : "=f"(r.x), "=f"(r.y) : "l"(v));
    return r;
}

// ---------------------------------------------------------------------------
// Kernel 1: ROI-align (bilinear, clamp) + 32x32 mean pool -> g_garf[24][64]
// grid (24, 64), 256 threads
// ---------------------------------------------------------------------------
__global__ void roi_garf_kernel(const float* __restrict__ imgs,
                                const float* __restrict__ pros,
                                const int* __restrict__ imgbatch) {
    int g = blockIdx.x;
    int c = blockIdx.y;
    int tid = threadIdx.x;
    int b = imgbatch[g];
    float px = pros[2 * g + 0];
    float py = pros[2 * g + 1];
    const float* im = imgs + ((size_t)(b * CCH + c)) * (IMH * IMW);

    float sum = 0.0f;
    #pragma unroll
    for (int s = tid; s < 1024; s += 256) {
        int i = s >> 5;
        int j = s & 31;
        float y = py - 16.0f + (float)i + 0.5f;
        float x = px - 16.0f + (float)j + 0.5f;
        float yf = floorf(y), xf = floorf(x);
        float wy = y - yf, wx = x - xf;
        int y0 = (int)yf, x0 = (int)xf;
        int y1 = y0 + 1, x1 = x0 + 1;
        y0 = min(max(y0, 0), IMH - 1);
        y1 = min(max(y1, 0), IMH - 1);
        x0 = min(max(x0, 0), IMW - 1);
        x1 = min(max(x1, 0), IMW - 1);
        float v00 = im[y0 * IMW + x0];
        float v01 = im[y0 * IMW + x1];
        float v10 = im[y1 * IMW + x0];
        float v11 = im[y1 * IMW + x1];
        sum += (1.0f - wy) * ((1.0f - wx) * v00 + wx * v01)
             +          wy * ((1.0f - wx) * v10 + wx * v11);
    }

    __shared__ float red[256];
    red[tid] = sum;
    __syncthreads();
    #pragma unroll
    for (int off = 128; off > 0; off >>= 1) {
        if (tid < off) red[tid] += red[tid + off];
        __syncthreads();
    }
    if (tid == 0) g_garf[g * CCH + c] = red[0] * (1.0f / 1024.0f);
}

// ---------------------------------------------------------------------------
// Kernel 2/3: tiled GEMM + ReLU.
// MODE 1: A = gathered feat [x_verts | garf], K=192, writes g_h1
// MODE 2: A = g_h1,                         K=256, writes g_h2
// Tile: 128x128x16, 256 threads, 8x8 micro-tile per thread, FFMA2 inner loop.
// grid: (sum ceil(M_t/128), 2)
// ---------------------------------------------------------------------------
template <int K, int MODE>
__global__ __launch_bounds__(256, 2)
void gemm_relu_kernel(const float* __restrict__ xv,
                      const int* __restrict__ gov,
                      const float* __restrict__ Wall,
                      P p) {
    __shared__ float As[16][132];
    __shared__ float Bs[16][132];

    int bx = blockIdx.x;
    int t = 0;
    while (t < NTYPES - 1 && bx >= p.tileOff[t + 1]) t++;
    int m0 = (bx - p.tileOff[t]) * 128;
    int n0 = blockIdx.y * 128;
    int Mt = p.M[t];
    const float* Wt = Wall + (size_t)t * K * HID;
    const int* idx = p.idx[t];
    int baseRow = p.rowOff[t];
    int tid = threadIdx.x;

    // A-load mapping: 2 threads per row, 8 consecutive k each
    int am = tid & 127;
    int ak = (tid >> 7) * 8;
    bool arowvalid = (m0 + am) < Mt;
    int av = 0, ag = 0;
    const float* Arow = nullptr;
    if (MODE == 1) {
        if (arowvalid) { av = idx[m0 + am]; ag = gov[av]; }
    } else {
        Arow = g_h1 + (size_t)(baseRow + m0 + am) * HID;
    }

    // B-load mapping: 16 threads per k-row, 8 consecutive n each
    int bk = tid >> 4;
    int bn = (tid & 15) * 8;

    // compute micro-tile coordinates
    int cty = tid >> 4;   // 0..15 (rows cty*4..+3 and 64+cty*4..+3)
    int ctx = tid & 15;   // 0..15 (cols ctx*4..+3 and 64+ctx*4..+3)

    unsigned long long acc[8][4];
    #pragma unroll
    for (int i = 0; i < 8; i++)
        #pragma unroll
        for (int j = 0; j < 4; j++) acc[i][j] = 0ull;

    for (int k0 = 0; k0 < K; k0 += 16) {
        // ---- load A tile (2048 elems) ----
        float4 a4[2];
        a4[0] = make_float4(0.f, 0.f, 0.f, 0.f);
        a4[1] = make_float4(0.f, 0.f, 0.f, 0.f);
        if (arowvalid) {
            if (MODE == 1) {
                int k = k0 + ak;   // multiple of 8; 128 boundary is too
                if (k < DV) {
                    a4[0] = *(const float4*)(xv + (size_t)av * DV + k);
                    a4[1] = *(const float4*)(xv + (size_t)av * DV + k + 4);
                } else {
                    a4[0] = *(const float4*)(g_garf + ag * CCH + (k - DV));
                    a4[1] = *(const float4*)(g_garf + ag * CCH + (k - DV) + 4);
                }
            } else {
                a4[0] = *(const float4*)(Arow + k0 + ak);
                a4[1] = *(const float4*)(Arow + k0 + ak + 4);
            }
        }
        #pragma unroll
        for (int h = 0; h < 2; h++) {
            As[ak + h * 4 + 0][am] = (&a4[h].x)[0];
            As[ak + h * 4 + 1][am] = (&a4[h].x)[1];
            As[ak + h * 4 + 2][am] = (&a4[h].x)[2];
            As[ak + h * 4 + 3][am] = (&a4[h].x)[3];
        }
        // ---- load B tile (2048 elems) ----
        {
            const float* src = Wt + (size_t)(k0 + bk) * HID + n0 + bn;
            float4 b40 = *(const float4*)(src);
            float4 b41 = *(const float4*)(src + 4);
            *(float4*)&Bs[bk][bn] = b40;
            *(float4*)&Bs[bk][bn + 4] = b41;
        }
        __syncthreads();

        // ---- compute ----
        #pragma unroll
        for (int k = 0; k < 16; k++) {
            float4 a0 = *(const float4*)&As[k][cty * 4];
            float4 a1 = *(const float4*)&As[k][64 + cty * 4];
            float4 b0 = *(const float4*)&Bs[k][ctx * 4];
            float4 b1 = *(const float4*)&Bs[k][64 + ctx * 4];
            unsigned long long bp0 = pk2(b0.x, b0.y);
            unsigned long long bp1 = pk2(b0.z, b0.w);
            unsigned long long bp2 = pk2(b1.x, b1.y);
            unsigned long long bp3 = pk2(b1.z, b1.w);
            float ar[8] = {a0.x, a0.y, a0.z, a0.w, a1.x, a1.y, a1.z, a1.w};
            #pragma unroll
            for (int i = 0; i < 8; i++) {
                unsigned long long ad = pk2(ar[i], ar[i]);
                fma2(acc[i][0], ad, bp0);
                fma2(acc[i][1], ad, bp1);
                fma2(acc[i][2], ad, bp2);
                fma2(acc[i][3], ad, bp3);
            }
        }
        __syncthreads();
    }

    // ---- epilogue: ReLU + store ----
    float* Obuf = (MODE == 1) ? g_h1 : g_h2;
    #pragma unroll
    for (int i = 0; i < 8; i++) {
        int r = (i < 4) ? (cty * 4 + i) : (64 + cty * 4 + (i - 4));
        int gr = m0 + r;
        if (gr < Mt) {
            float o[8];
            #pragma unroll
            for (int j = 0; j < 4; j++) {
                float2 q = upk2(acc[i][j]);
                o[2 * j + 0] = fmaxf(q.x, 0.0f);
                o[2 * j + 1] = fmaxf(q.y, 0.0f);
            }
            float* dst = Obuf + (size_t)(baseRow + gr) * HID + n0;
            *(float4*)(dst + ctx * 4)      = make_float4(o[0], o[1], o[2], o[3]);
            *(float4*)(dst + 64 + ctx * 4) = make_float4(o[4], o[5], o[6], o[7]);
        }
    }
}

// ---------------------------------------------------------------------------
// Kernel 4: layer 3 (256 -> 3) + scatter to out[idx]. One warp per row.
// ---------------------------------------------------------------------------
__global__ void gemm3_kernel(const float* __restrict__ W3,
                             float* __restrict__ out,
                             P p, int Ntot) {
    int warp = (int)((blockIdx.x * blockDim.x + threadIdx.x) >> 5);
    int lane = threadIdx.x & 31;
    if (warp >= Ntot) return;
    int t = 0;
    while (t < NTYPES - 1 && warp >= p.rowOff[t + 1]) t++;
    const float* W3t = W3 + t * (HID * 3);
    const float* hrow = g_h2 + (size_t)warp * HID;

    float a0 = 0.f, a1 = 0.f, a2 = 0.f;
    #pragma unroll
    for (int u = 0; u < 8; u++) {
        int k = u * 32 + lane;
        float h = hrow[k];
        a0 += h * W3t[k * 3 + 0];
        a1 += h * W3t[k * 3 + 1];
        a2 += h * W3t[k * 3 + 2];
    }
    #pragma unroll
    for (int off = 16; off > 0; off >>= 1) {
        a0 += __shfl_xor_sync(0xFFFFFFFFu, a0, off);
        a1 += __shfl_xor_sync(0xFFFFFFFFu, a1, off);
        a2 += __shfl_xor_sync(0xFFFFFFFFu, a2, off);
    }
    if (lane == 0) {
        int v = p.idx[t][warp - p.rowOff[t]];
        out[(size_t)v * 3 + 0] = a0;
        out[(size_t)v * 3 + 1] = a1;
        out[(size_t)v * 3 + 2] = a2;
    }
}

// ---------------------------------------------------------------------------
// Launch
// ---------------------------------------------------------------------------
extern "C" void kernel_launch(void* const* d_in, const int* in_sizes, int n_in,
                              void* d_out, int out_size) {
    const float* imgs     = (const float*)d_in[0];
    const float* pros     = (const float*)d_in[1];
    const float* x_verts  = (const float*)d_in[2];
    const float* W1       = (const float*)d_in[3];
    const float* W2       = (const float*)d_in[4];
    const float* W3       = (const float*)d_in[5];
    const int*   imgbatch = (const int*)d_in[6];
    const int*   gov      = (const int*)d_in[7];
    float*       out      = (float*)d_out;

    P p;
    p.rowOff[0] = 0;
    p.tileOff[0] = 0;
    for (int t = 0; t < NTYPES; t++) {
        p.idx[t] = (const int*)d_in[8 + t];
        p.M[t] = in_sizes[8 + t];
        p.rowOff[t + 1] = p.rowOff[t] + p.M[t];
        p.tileOff[t + 1] = p.tileOff[t] + (p.M[t] + 127) / 128;
    }
    int Ntot = p.rowOff[NTYPES];

    dim3 gG(GARM, CCH);
    roi_garf_kernel<<<gG, 256>>>(imgs, pros, imgbatch);

    dim3 gM(p.tileOff[NTYPES], 2);
    gemm_relu_kernel<DIN, 1><<<gM, 256>>>(x_verts, gov, W1, p);
    gemm_relu_kernel<HID, 2><<<gM, 256>>>(x_verts, gov, W2, p);

    int blocks3 = (Ntot + 7) / 8;  // 8 warps per 256-thread block
    gemm3_kernel<<<blocks3, 256>>>(W3, out, p, Ntot);
}

// round 3
// speedup vs baseline: 1.5829x; 1.5829x over previous
#include <cuda_runtime.h>
#include <cuda_bf16.h>
#include <cstdint>
#include <cstddef>

// ---------------------------------------------------------------------------
// Problem constants
// ---------------------------------------------------------------------------
#define NTYPES 6
#define HID    256
#define DV     128
#define CCH    64
#define IMH    192
#define IMW    192
#define GARM   24
#define MAXTILES 816   // sum ceil(M_t/128) <= 809 for this dataset; pad a little

// ---------------------------------------------------------------------------
// Static device scratch. Blob = the exact SMEM image a GEMM tile load wants:
//  A tile image: 128 rows x 64 bf16 (128B/row), SW128-swizzled -> 16KB = 1024 uint4
//  B tile image: 256 rows (n) x 64 bf16 (k)  -> 32KB = 2048 uint4   (B^T layout)
// ---------------------------------------------------------------------------
__device__ float g_garf[GARM * CCH];
__device__ uint4 g_fa_hi[(size_t)MAXTILES * 3 * 1024];
__device__ uint4 g_fa_lo[(size_t)MAXTILES * 3 * 1024];
__device__ uint4 g_h1_hi[(size_t)MAXTILES * 4 * 1024];
__device__ uint4 g_h1_lo[(size_t)MAXTILES * 4 * 1024];
__device__ uint4 g_B1_hi[6 * 3 * 2048];
__device__ uint4 g_B1_lo[6 * 3 * 2048];
__device__ uint4 g_B2_hi[6 * 4 * 2048];
__device__ uint4 g_B2_lo[6 * 4 * 2048];

struct P {
    const int* idx[NTYPES];
    int M[NTYPES];
    int rowOff[NTYPES + 1];
    int tileOff[NTYPES + 1];
};

// ---------------------------------------------------------------------------
// Helpers (base-arch PTX only: ldmatrix / mma.sync / cp.async — all sm_80+)
// ---------------------------------------------------------------------------
__device__ __forceinline__ uint32_t smem_u32(const void* p) {
    uint32_t a;
    asm("{ .reg .u64 t; cvta.to.shared.u64 t, %1; cvt.u32.u64 %0, t; }" : "=r"(a) : "l"(p));
    return a;
}
#define SW128(x) ((x) ^ (((x) >> 3) & 0x70))

__device__ __forceinline__ void cpa16(uint32_t s, const void* g) {
    asm volatile("cp.async.cg.shared.global [%0], [%1], 16;" :: "r"(s), "l"(g));
}
#define CP_COMMIT() asm volatile("cp.async.commit_group;" ::: "memory")
#define CP_WAIT0()  asm volatile("cp.async.wait_group 0;" ::: "memory")

__device__ __forceinline__ void ldm_x4(uint32_t& r0, uint32_t& r1, uint32_t& r2, uint32_t& r3, uint32_t addr) {
    asm volatile("ldmatrix.sync.aligned.m8n8.x4.shared.b16 {%0,%1,%2,%3}, [%4];"
                 : "=r"(r0), "=r"(r1), "=r"(r2), "=r"(r3) : "r"(addr));
}
__device__ __forceinline__ void mma16816(float* d, const uint32_t* a, uint32_t b0, uint32_t b1) {
    asm volatile(
        "mma.sync.aligned.m16n8k16.row.col.f32.bf16.bf16.f32 "
        "{%0,%1,%2,%3},{%4,%5,%6,%7},{%8,%9},{%0,%1,%2,%3};"
        : "+f"(d[0]), "+f"(d[1]), "+f"(d[2]), "+f"(d[3])
        : "r"(a[0]), "r"(a[1]), "r"(a[2]), "r"(a[3]), "r"(b0), "r"(b1));
}
__device__ __forceinline__ void sts32(uint32_t addr, uint32_t v) {
    asm volatile("st.shared.b32 [%0], %1;" :: "r"(addr), "r"(v) : "memory");
}

// bf16 hi/lo split + pack
__device__ __forceinline__ void bsplit(float x, uint16_t& h, uint16_t& l) {
    __nv_bfloat16 hb = __float2bfloat16_rn(x);
    float hf = __bfloat162float(hb);
    __nv_bfloat16 lb = __float2bfloat16_rn(x - hf);
    h = *reinterpret_cast<uint16_t*>(&hb);
    l = *reinterpret_cast<uint16_t*>(&lb);
}
__device__ __forceinline__ uint32_t pk16(uint16_t a, uint16_t b) {
    return (uint32_t)a | ((uint32_t)b << 16);
}
__device__ __forceinline__ void split8(const float* v, uint4& hq, uint4& lq) {
    uint16_t h[8], l[8];
    #pragma unroll
    for (int i = 0; i < 8; i++) bsplit(v[i], h[i], l[i]);
    hq = make_uint4(pk16(h[0], h[1]), pk16(h[2], h[3]), pk16(h[4], h[5]), pk16(h[6], h[7]));
    lq = make_uint4(pk16(l[0], l[1]), pk16(l[2], l[3]), pk16(l[4], l[5]), pk16(l[6], l[7]));
}

// ---------------------------------------------------------------------------
// Kernel 1: ROI-align + mean pool -> g_garf
// ---------------------------------------------------------------------------
__global__ void roi_garf_kernel(const float* __restrict__ imgs,
                                const float* __restrict__ pros,
                                const int* __restrict__ imgbatch) {
    int g = blockIdx.x, c = blockIdx.y, tid = threadIdx.x;
    int b = imgbatch[g];
    float px = pros[2 * g + 0], py = pros[2 * g + 1];
    const float* im = imgs + ((size_t)(b * CCH + c)) * (IMH * IMW);
    float sum = 0.0f;
    #pragma unroll
    for (int s = tid; s < 1024; s += 256) {
        int i = s >> 5, j = s & 31;
        float y = py - 16.0f + (float)i + 0.5f;
        float x = px - 16.0f + (float)j + 0.5f;
        float yf = floorf(y), xf = floorf(x);
        float wy = y - yf, wx = x - xf;
        int y0 = (int)yf, x0 = (int)xf, y1, x1;
        y1 = min(max(y0 + 1, 0), IMH - 1); x1 = min(max(x0 + 1, 0), IMW - 1);
        y0 = min(max(y0, 0), IMH - 1);     x0 = min(max(x0, 0), IMW - 1);
        float v00 = im[y0 * IMW + x0], v01 = im[y0 * IMW + x1];
        float v10 = im[y1 * IMW + x0], v11 = im[y1 * IMW + x1];
        sum += (1.0f - wy) * ((1.0f - wx) * v00 + wx * v01)
             +          wy * ((1.0f - wx) * v10 + wx * v11);
    }
    __shared__ float red[256];
    red[tid] = sum;
    __syncthreads();
    #pragma unroll
    for (int off = 128; off > 0; off >>= 1) {
        if (tid < off) red[tid] += red[tid + off];
        __syncthreads();
    }
    if (tid == 0) g_garf[g * CCH + c] = red[0] * (1.0f / 1024.0f);
}

// ---------------------------------------------------------------------------
// Kernel 2: weight images. grid (6, 7): y<3 -> layer1 chunk y, else layer2 y-3.
// Blob row n (0..255), col k (0..63), value = W[t][c*64+k][n] (B^T).
// ---------------------------------------------------------------------------
__global__ void wimg_kernel(const float* __restrict__ W1, const float* __restrict__ W2) {
    int t = blockIdx.x, cc = blockIdx.y, n = threadIdx.x;
    const float* W;
    uint4 *dh, *dl;
    int c;
    if (cc < 3) {
        c = cc;
        W = W1 + (size_t)t * 192 * 256;
        dh = g_B1_hi + (size_t)(t * 3 + c) * 2048;
        dl = g_B1_lo + (size_t)(t * 3 + c) * 2048;
    } else {
        c = cc - 3;
        W = W2 + (size_t)t * 256 * 256;
        dh = g_B2_hi + (size_t)(t * 4 + c) * 2048;
        dl = g_B2_lo + (size_t)(t * 4 + c) * 2048;
    }
    #pragma unroll
    for (int g4 = 0; g4 < 8; g4++) {
        float v[8];
        #pragma unroll
        for (int i = 0; i < 8; i++) v[i] = W[(size_t)(c * 64 + g4 * 8 + i) * 256 + n];
        uint4 hq, lq;
        split8(v, hq, lq);
        uint32_t sw = SW128((uint32_t)(n * 128 + g4 * 16));
        dh[sw >> 4] = hq;
        dl[sw >> 4] = lq;
    }
}

// ---------------------------------------------------------------------------
// Kernel 3: feature images. grid = tiles, 128 threads, one row each.
// feat[row] = [x_verts[v] | garf[gov[v]]], split to bf16 hi/lo blobs.
// ---------------------------------------------------------------------------
__global__ void featimg_kernel(const float* __restrict__ xv,
                               const int* __restrict__ gov, P p) {
    int mt = blockIdx.x, r = threadIdx.x;
    int t = 0;
    while (t < NTYPES - 1 && mt >= p.tileOff[t + 1]) t++;
    int grow = (mt - p.tileOff[t]) * 128 + r;
    bool valid = grow < p.M[t];
    int v = valid ? p.idx[t][grow] : 0;
    int g = valid ? gov[v] : 0;
    #pragma unroll
    for (int c = 0; c < 3; c++) {
        const float* src = (c < 2) ? (xv + (size_t)v * DV + c * 64) : (g_garf + g * CCH);
        uint4* dh = g_fa_hi + (size_t)(mt * 3 + c) * 1024;
        uint4* dl = g_fa_lo + (size_t)(mt * 3 + c) * 1024;
        #pragma unroll
        for (int g4 = 0; g4 < 8; g4++) {
            float v8[8];
            if (valid) {
                float4 f0 = *(const float4*)(src + g4 * 8);
                float4 f1 = *(const float4*)(src + g4 * 8 + 4);
                v8[0] = f0.x; v8[1] = f0.y; v8[2] = f0.z; v8[3] = f0.w;
                v8[4] = f1.x; v8[5] = f1.y; v8[6] = f1.z; v8[7] = f1.w;
            } else {
                #pragma unroll
                for (int i = 0; i < 8; i++) v8[i] = 0.0f;
            }
            uint4 hq, lq;
            split8(v8, hq, lq);
            uint32_t sw = SW128((uint32_t)(r * 128 + g4 * 16));
            dh[sw >> 4] = hq;
            dl[sw >> 4] = lq;
        }
    }
}

// ---------------------------------------------------------------------------
// Kernel 4/5: mma.sync GEMM, 128x128 tile per CTA (grid.y = N half),
// 3-pass bf16 hi/lo split, fp32 accumulation.
// MODE 1: A = feat blobs (3 chunks),  epilogue relu+split -> h1 blobs
// MODE 2: A = h1 blobs (4 chunks),    epilogue relu + fused layer3 + atomic scatter
// 256 threads = 8 warps of 64x32 warp tiles.
// ---------------------------------------------------------------------------
template <int CHUNKS, int MODE>
__global__ __launch_bounds__(256, 2)
void gemm_mma_kernel(const float* __restrict__ W3, float* __restrict__ out, P p) {
    extern __shared__ char dsm[];
    int tid = threadIdx.x, lane = tid & 31, wid = tid >> 5;
    int wm = wid >> 2, wn = wid & 3;
    int mt = blockIdx.x, by = blockIdx.y;
    int t = 0;
    while (t < NTYPES - 1 && mt >= p.tileOff[t + 1]) t++;
    int m0 = (mt - p.tileOff[t]) * 128;
    int Mt = p.M[t];

    uint32_t sbraw = smem_u32(dsm);
    uint32_t s0 = (sbraw + 1023u) & ~1023u;
    char* al = dsm + (s0 - sbraw);
    uint32_t sAh = s0, sAl = s0 + 16384, sBh = s0 + 32768, sBl = s0 + 49152;

    // W3 columns owned by this thread (MODE 2 only)
    float w3r[4][2][3];
    if (MODE == 2) {
        #pragma unroll
        for (int nf = 0; nf < 4; nf++) {
            int nc = by * 128 + wn * 32 + nf * 8 + 2 * (lane & 3);
            #pragma unroll
            for (int u = 0; u < 2; u++)
                #pragma unroll
                for (int j = 0; j < 3; j++)
                    w3r[nf][u][j] = W3[(size_t)t * (HID * 3) + (nc + u) * 3 + j];
        }
    }

    float acc[4][4][4];
    #pragma unroll
    for (int i = 0; i < 4; i++)
        #pragma unroll
        for (int j = 0; j < 4; j++)
            #pragma unroll
            for (int k = 0; k < 4; k++) acc[i][j][k] = 0.0f;

    // per-lane ldmatrix addressing
    int aRow = lane & 15;               // row within m16 tile
    int aKext = (lane >> 4) * 16;       // second k8 group for lanes 16-31
    int bRow = ((lane >> 4) << 3) + (lane & 7);  // n row within n16 group
    int bKext = ((lane >> 3) & 1) * 16; // k8 group toggles every 8 lanes
    int xr = (lane & 7) * 16;           // SW128 xor term (row & 7) * 16
    uint32_t aBase[4], bBase[2];
    #pragma unroll
    for (int mf = 0; mf < 4; mf++) aBase[mf] = (uint32_t)((wm * 64 + mf * 16 + aRow) * 128);
    #pragma unroll
    for (int n2 = 0; n2 < 2; n2++) bBase[n2] = (uint32_t)((wn * 32 + n2 * 16 + bRow) * 128);

    for (int c = 0; c < CHUNKS; c++) {
        const uint4 *Ah, *Al, *Bh, *Bl;
        if (MODE == 1) {
            Ah = g_fa_hi + (size_t)(mt * 3 + c) * 1024;
            Al = g_fa_lo + (size_t)(mt * 3 + c) * 1024;
            Bh = g_B1_hi + (size_t)(t * 3 + c) * 2048 + (size_t)by * 1024;
            Bl = g_B1_lo + (size_t)(t * 3 + c) * 2048 + (size_t)by * 1024;
        } else {
            Ah = g_h1_hi + (size_t)(mt * 4 + c) * 1024;
            Al = g_h1_lo + (size_t)(mt * 4 + c) * 1024;
            Bh = g_B2_hi + (size_t)(t * 4 + c) * 2048 + (size_t)by * 1024;
            Bl = g_B2_lo + (size_t)(t * 4 + c) * 2048 + (size_t)by * 1024;
        }
        #pragma unroll
        for (int i = tid; i < 1024; i += 256) {
            cpa16(sAh + i * 16, Ah + i);
            cpa16(sAl + i * 16, Al + i);
            cpa16(sBh + i * 16, Bh + i);
            cpa16(sBl + i * 16, Bl + i);
        }
        CP_COMMIT();
        CP_WAIT0();
        __syncthreads();

        #pragma unroll
        for (int pass = 0; pass < 3; pass++) {
            uint32_t sA = (pass == 1) ? sAl : sAh;
            uint32_t sB = (pass == 2) ? sBl : sBh;
            #pragma unroll
            for (int k16 = 0; k16 < 4; k16++) {
                int kb = k16 * 32;
                uint32_t a[4][4], b[2][4];
                #pragma unroll
                for (int mf = 0; mf < 4; mf++)
                    ldm_x4(a[mf][0], a[mf][1], a[mf][2], a[mf][3],
                           sA + aBase[mf] + (uint32_t)((kb + aKext) ^ xr));
                #pragma unroll
                for (int n2 = 0; n2 < 2; n2++)
                    ldm_x4(b[n2][0], b[n2][1], b[n2][2], b[n2][3],
                           sB + bBase[n2] + (uint32_t)((kb + bKext) ^ xr));
                #pragma unroll
                for (int mf = 0; mf < 4; mf++)
                    #pragma unroll
                    for (int nf = 0; nf < 4; nf++)
                        mma16816(acc[mf][nf], a[mf],
                                 b[nf >> 1][(nf & 1) * 2], b[nf >> 1][(nf & 1) * 2 + 1]);
            }
        }
        __syncthreads();
    }

    if (MODE == 1) {
        // relu + bf16 split, staged through smem, then coalesced blob write
        #pragma unroll
        for (int mf = 0; mf < 4; mf++) {
            #pragma unroll
            for (int nf = 0; nf < 4; nf++) {
                int R0 = wm * 64 + mf * 16 + (lane >> 2);
                int nl = wn * 32 + nf * 8 + 2 * (lane & 3);
                int loc = nl >> 6, ncl = nl & 63;
                float c0 = fmaxf(acc[mf][nf][0], 0.0f);
                float c1 = fmaxf(acc[mf][nf][1], 0.0f);
                float c2 = fmaxf(acc[mf][nf][2], 0.0f);
                float c3 = fmaxf(acc[mf][nf][3], 0.0f);
                uint16_t h0, l0, h1, l1, h2, l2, h3, l3;
                bsplit(c0, h0, l0); bsplit(c1, h1, l1);
                bsplit(c2, h2, l2); bsplit(c3, h3, l3);
                uint32_t off0 = SW128((uint32_t)(R0 * 128 + ncl * 2));
                uint32_t off1 = SW128((uint32_t)((R0 + 8) * 128 + ncl * 2));
                uint32_t hbase = s0 + loc * 16384;
                uint32_t lbase = s0 + 32768 + loc * 16384;
                sts32(hbase + off0, pk16(h0, h1));
                sts32(hbase + off1, pk16(h2, h3));
                sts32(lbase + off0, pk16(l0, l1));
                sts32(lbase + off1, pk16(l2, l3));
            }
        }
        __syncthreads();
        const uint4* sh = (const uint4*)al;
        const uint4* sl = (const uint4*)(al + 32768);
        #pragma unroll
        for (int i = tid; i < 2048; i += 256) {
            int cg = by * 2 + (i >> 10);
            g_h1_hi[(size_t)(mt * 4 + cg) * 1024 + (i & 1023)] = sh[i];
            g_h1_lo[(size_t)(mt * 4 + cg) * 1024 + (i & 1023)] = sl[i];
        }
    } else {
        // relu + fused layer-3 dot + atomic scatter (out pre-zeroed)
        #pragma unroll
        for (int mf = 0; mf < 4; mf++) {
            float s0v[3] = {0.f, 0.f, 0.f}, s1v[3] = {0.f, 0.f, 0.f};
            #pragma unroll
            for (int nf = 0; nf < 4; nf++) {
                float h0 = fmaxf(acc[mf][nf][0], 0.0f);
                float h1 = fmaxf(acc[mf][nf][1], 0.0f);
                float h2 = fmaxf(acc[mf][nf][2], 0.0f);
                float h3 = fmaxf(acc[mf][nf][3], 0.0f);
                #pragma unroll
                for (int j = 0; j < 3; j++) {
                    s0v[j] += h0 * w3r[nf][0][j] + h1 * w3r[nf][1][j];
                    s1v[j] += h2 * w3r[nf][0][j] + h3 * w3r[nf][1][j];
                }
            }
            #pragma unroll
            for (int j = 0; j < 3; j++) {
                #pragma unroll
                for (int off = 1; off <= 2; off <<= 1) {
                    s0v[j] += __shfl_xor_sync(0xFFFFFFFFu, s0v[j], off);
                    s1v[j] += __shfl_xor_sync(0xFFFFFFFFu, s1v[j], off);
                }
            }
            if ((lane & 3) == 0) {
                int R0 = wm * 64 + mf * 16 + (lane >> 2);
                int g0 = m0 + R0, g1 = g0 + 8;
                if (g0 < Mt) {
                    int v = p.idx[t][g0];
                    #pragma unroll
                    for (int j = 0; j < 3; j++) atomicAdd(&out[(size_t)v * 3 + j], s0v[j]);
                }
                if (g1 < Mt) {
                    int v = p.idx[t][g1];
                    #pragma unroll
                    for (int j = 0; j < 3; j++) atomicAdd(&out[(size_t)v * 3 + j], s1v[j]);
                }
            }
        }
    }
}

// ---------------------------------------------------------------------------
// Launch
// ---------------------------------------------------------------------------
#define GEMM_SMEM (65536 + 1024)

extern "C" void kernel_launch(void* const* d_in, const int* in_sizes, int n_in,
                              void* d_out, int out_size) {
    const float* imgs     = (const float*)d_in[0];
    const float* pros     = (const float*)d_in[1];
    const float* x_verts  = (const float*)d_in[2];
    const float* W1       = (const float*)d_in[3];
    const float* W2       = (const float*)d_in[4];
    const float* W3       = (const float*)d_in[5];
    const int*   imgbatch = (const int*)d_in[6];
    const int*   gov      = (const int*)d_in[7];
    float*       out      = (float*)d_out;

    P p;
    p.rowOff[0] = 0;
    p.tileOff[0] = 0;
    for (int t = 0; t < NTYPES; t++) {
        p.idx[t] = (const int*)d_in[8 + t];
        p.M[t] = in_sizes[8 + t];
        p.rowOff[t + 1] = p.rowOff[t] + p.M[t];
        p.tileOff[t + 1] = p.tileOff[t] + (p.M[t] + 127) / 128;
    }
    int tiles = p.tileOff[NTYPES];

    cudaFuncSetAttribute(gemm_mma_kernel<3, 1>, cudaFuncAttributeMaxDynamicSharedMemorySize, GEMM_SMEM);
    cudaFuncSetAttribute(gemm_mma_kernel<4, 2>, cudaFuncAttributeMaxDynamicSharedMemorySize, GEMM_SMEM);

    // zero the output (layer-3 scatter accumulates with atomics)
    cudaMemsetAsync(d_out, 0, (size_t)out_size * sizeof(float), 0);

    dim3 gG(GARM, CCH);
    roi_garf_kernel<<<gG, 256>>>(imgs, pros, imgbatch);

    dim3 gW(6, 7);
    wimg_kernel<<<gW, 256>>>(W1, W2);

    featimg_kernel<<<tiles, 128>>>(x_verts, gov, p);

    dim3 gM(tiles, 2);
    gemm_mma_kernel<3, 1><<<gM, 256, GEMM_SMEM>>>(W3, out, p);
    gemm_mma_kernel<4, 2><<<gM, 256, GEMM_SMEM>>>(W3, out, p);
}

// round 4
// speedup vs baseline: 1.8105x; 1.1438x over previous
#include <cuda_runtime.h>
#include <cuda_bf16.h>
#include <cstdint>
#include <cstddef>

// ---------------------------------------------------------------------------
// Problem constants
// ---------------------------------------------------------------------------
#define NTYPES 6
#define HID    256
#define DV     128
#define CCH    64
#define IMH    192
#define IMW    192
#define GARM   24
#define MAXTILES 816   // sum ceil(M_t/128) <= 809; pad a little

// ---------------------------------------------------------------------------
// Static device scratch. Blob = the exact SMEM image a GEMM tile load wants:
//  A tile image: 128 rows x 64 bf16 (128B/row), SW128-swizzled -> 16KB = 1024 uint4
//  B tile image: 256 rows (n) x 64 bf16 (k)  -> 32KB = 2048 uint4   (B^T layout)
// ---------------------------------------------------------------------------
__device__ float g_garf[GARM * CCH];
__device__ uint4 g_fa_hi[(size_t)MAXTILES * 3 * 1024];
__device__ uint4 g_fa_lo[(size_t)MAXTILES * 3 * 1024];
__device__ uint4 g_h1_hi[(size_t)MAXTILES * 4 * 1024];
__device__ uint4 g_h1_lo[(size_t)MAXTILES * 4 * 1024];
__device__ uint4 g_B1_hi[6 * 3 * 2048];
__device__ uint4 g_B1_lo[6 * 3 * 2048];
__device__ uint4 g_B2_hi[6 * 4 * 2048];
__device__ uint4 g_B2_lo[6 * 4 * 2048];

struct P {
    const int* idx[NTYPES];
    int M[NTYPES];
    int rowOff[NTYPES + 1];
    int tileOff[NTYPES + 1];
};

// ---------------------------------------------------------------------------
// Helpers (base-arch PTX only: ldmatrix / mma.sync / cp.async — all sm_80+)
// ---------------------------------------------------------------------------
__device__ __forceinline__ uint32_t smem_u32(const void* p) {
    uint32_t a;
    asm("{ .reg .u64 t; cvta.to.shared.u64 t, %1; cvt.u32.u64 %0, t; }" : "=r"(a) : "l"(p));
    return a;
}
#define SW128(x) ((x) ^ (((x) >> 3) & 0x70))

__device__ __forceinline__ void cpa16(uint32_t s, const void* g) {
    asm volatile("cp.async.cg.shared.global [%0], [%1], 16;" :: "r"(s), "l"(g));
}
#define CP_COMMIT() asm volatile("cp.async.commit_group;" ::: "memory")
#define CP_WAIT0()  asm volatile("cp.async.wait_group 0;" ::: "memory")
#define CP_WAIT1()  asm volatile("cp.async.wait_group 1;" ::: "memory")

__device__ __forceinline__ void ldm_x4(uint32_t* r, uint32_t addr) {
    asm volatile("ldmatrix.sync.aligned.m8n8.x4.shared.b16 {%0,%1,%2,%3}, [%4];"
                 : "=r"(r[0]), "=r"(r[1]), "=r"(r[2]), "=r"(r[3]) : "r"(addr));
}
__device__ __forceinline__ void mma16816(float* d, const uint32_t* a, uint32_t b0, uint32_t b1) {
    asm volatile(
        "mma.sync.aligned.m16n8k16.row.col.f32.bf16.bf16.f32 "
        "{%0,%1,%2,%3},{%4,%5,%6,%7},{%8,%9},{%0,%1,%2,%3};"
        : "+f"(d[0]), "+f"(d[1]), "+f"(d[2]), "+f"(d[3])
        : "r"(a[0]), "r"(a[1]), "r"(a[2]), "r"(a[3]), "r"(b0), "r"(b1));
}
__device__ __forceinline__ void sts32(uint32_t addr, uint32_t v) {
    asm volatile("st.shared.b32 [%0], %1;" :: "r"(addr), "r"(v) : "memory");
}

// bf16 hi/lo split + pack
__device__ __forceinline__ void bsplit(float x, uint16_t& h, uint16_t& l) {
    __nv_bfloat16 hb = __float2bfloat16_rn(x);
    float hf = __bfloat162float(hb);
    __nv_bfloat16 lb = __float2bfloat16_rn(x - hf);
    h = *reinterpret_cast<uint16_t*>(&hb);
    l = *reinterpret_cast<uint16_t*>(&lb);
}
__device__ __forceinline__ uint32_t pk16(uint16_t a, uint16_t b) {
    return (uint32_t)a | ((uint32_t)b << 16);
}
__device__ __forceinline__ void split8(const float* v, uint4& hq, uint4& lq) {
    uint16_t h[8], l[8];
    #pragma unroll
    for (int i = 0; i < 8; i++) bsplit(v[i], h[i], l[i]);
    hq = make_uint4(pk16(h[0], h[1]), pk16(h[2], h[3]), pk16(h[4], h[5]), pk16(h[6], h[7]));
    lq = make_uint4(pk16(l[0], l[1]), pk16(l[2], l[3]), pk16(l[4], l[5]), pk16(l[6], l[7]));
}

// ---------------------------------------------------------------------------
// Kernel 1: ROI-align + mean pool -> g_garf
// ---------------------------------------------------------------------------
__global__ void roi_garf_kernel(const float* __restrict__ imgs,
                                const float* __restrict__ pros,
                                const int* __restrict__ imgbatch) {
    int g = blockIdx.x, c = blockIdx.y, tid = threadIdx.x;
    int b = imgbatch[g];
    float px = pros[2 * g + 0], py = pros[2 * g + 1];
    const float* im = imgs + ((size_t)(b * CCH + c)) * (IMH * IMW);
    float sum = 0.0f;
    #pragma unroll
    for (int s = tid; s < 1024; s += 256) {
        int i = s >> 5, j = s & 31;
        float y = py - 16.0f + (float)i + 0.5f;
        float x = px - 16.0f + (float)j + 0.5f;
        float yf = floorf(y), xf = floorf(x);
        float wy = y - yf, wx = x - xf;
        int y0 = (int)yf, x0 = (int)xf, y1, x1;
        y1 = min(max(y0 + 1, 0), IMH - 1); x1 = min(max(x0 + 1, 0), IMW - 1);
        y0 = min(max(y0, 0), IMH - 1);     x0 = min(max(x0, 0), IMW - 1);
        float v00 = im[y0 * IMW + x0], v01 = im[y0 * IMW + x1];
        float v10 = im[y1 * IMW + x0], v11 = im[y1 * IMW + x1];
        sum += (1.0f - wy) * ((1.0f - wx) * v00 + wx * v01)
             +          wy * ((1.0f - wx) * v10 + wx * v11);
    }
    __shared__ float red[256];
    red[tid] = sum;
    __syncthreads();
    #pragma unroll
    for (int off = 128; off > 0; off >>= 1) {
        if (tid < off) red[tid] += red[tid + off];
        __syncthreads();
    }
    if (tid == 0) g_garf[g * CCH + c] = red[0] * (1.0f / 1024.0f);
}

// ---------------------------------------------------------------------------
// Kernel 2: weight images. grid (6, 7): y<3 -> layer1 chunk y, else layer2 y-3.
// ---------------------------------------------------------------------------
__global__ void wimg_kernel(const float* __restrict__ W1, const float* __restrict__ W2) {
    int t = blockIdx.x, cc = blockIdx.y, n = threadIdx.x;
    const float* W;
    uint4 *dh, *dl;
    int c;
    if (cc < 3) {
        c = cc;
        W = W1 + (size_t)t * 192 * 256;
        dh = g_B1_hi + (size_t)(t * 3 + c) * 2048;
        dl = g_B1_lo + (size_t)(t * 3 + c) * 2048;
    } else {
        c = cc - 3;
        W = W2 + (size_t)t * 256 * 256;
        dh = g_B2_hi + (size_t)(t * 4 + c) * 2048;
        dl = g_B2_lo + (size_t)(t * 4 + c) * 2048;
    }
    #pragma unroll
    for (int g4 = 0; g4 < 8; g4++) {
        float v[8];
        #pragma unroll
        for (int i = 0; i < 8; i++) v[i] = W[(size_t)(c * 64 + g4 * 8 + i) * 256 + n];
        uint4 hq, lq;
        split8(v, hq, lq);
        uint32_t sw = SW128((uint32_t)(n * 128 + g4 * 16));
        dh[sw >> 4] = hq;
        dl[sw >> 4] = lq;
    }
}

// ---------------------------------------------------------------------------
// Kernel 3: feature images. grid = tiles, 128 threads, one row each.
// ---------------------------------------------------------------------------
__global__ void featimg_kernel(const float* __restrict__ xv,
                               const int* __restrict__ gov, P p) {
    int mt = blockIdx.x, r = threadIdx.x;
    int t = 0;
    while (t < NTYPES - 1 && mt >= p.tileOff[t + 1]) t++;
    int grow = (mt - p.tileOff[t]) * 128 + r;
    bool valid = grow < p.M[t];
    int v = valid ? p.idx[t][grow] : 0;
    int g = valid ? gov[v] : 0;
    #pragma unroll
    for (int c = 0; c < 3; c++) {
        const float* src = (c < 2) ? (xv + (size_t)v * DV + c * 64) : (g_garf + g * CCH);
        uint4* dh = g_fa_hi + (size_t)(mt * 3 + c) * 1024;
        uint4* dl = g_fa_lo + (size_t)(mt * 3 + c) * 1024;
        #pragma unroll
        for (int g4 = 0; g4 < 8; g4++) {
            float v8[8];
            if (valid) {
                float4 f0 = *(const float4*)(src + g4 * 8);
                float4 f1 = *(const float4*)(src + g4 * 8 + 4);
                v8[0] = f0.x; v8[1] = f0.y; v8[2] = f0.z; v8[3] = f0.w;
                v8[4] = f1.x; v8[5] = f1.y; v8[6] = f1.z; v8[7] = f1.w;
            } else {
                #pragma unroll
                for (int i = 0; i < 8; i++) v8[i] = 0.0f;
            }
            uint4 hq, lq;
            split8(v8, hq, lq);
            uint32_t sw = SW128((uint32_t)(r * 128 + g4 * 16));
            dh[sw >> 4] = hq;
            dl[sw >> 4] = lq;
        }
    }
}

// ---------------------------------------------------------------------------
// Kernel 4/5: double-buffered mma.sync GEMM.
// CTA = 128x128 output tile (grid = (2 n-halves, tiles)), 512 threads,
// 16 warps of 32x32 warp tiles. 3-pass bf16 hi/lo, fp32 accum.
// Pipeline: 2 smem stages x 64KB; prefetch chunk c+1 while computing c.
// MODE 1: A = feat blobs (3 chunks), epilogue relu+split -> h1 blobs
// MODE 2: A = h1 blobs (4 chunks), epilogue relu + fused layer3 + atomic scatter
// ---------------------------------------------------------------------------
#define STAGE_BYTES 65536

template <int CHUNKS, int MODE>
__global__ __launch_bounds__(512, 1)
void gemm_mma_kernel(const float* __restrict__ W3, float* __restrict__ out, P p) {
    extern __shared__ char dsm[];
    int tid = threadIdx.x, lane = tid & 31, wid = tid >> 5;
    int wm = wid >> 2, wn = wid & 3;              // 4x4 warp grid, 32x32 tiles
    int by = blockIdx.x, mt = blockIdx.y;
    int t = 0;
    while (t < NTYPES - 1 && mt >= p.tileOff[t + 1]) t++;
    int m0 = (mt - p.tileOff[t]) * 128;
    int Mt = p.M[t];

    uint32_t sbraw = smem_u32(dsm);
    uint32_t s0 = (sbraw + 1023u) & ~1023u;
    char* alp = dsm + (s0 - sbraw);

    // W3 columns owned by this thread (MODE 2 only)
    float w3r[4][2][3];
    if (MODE == 2) {
        #pragma unroll
        for (int nf = 0; nf < 4; nf++) {
            int nc = by * 128 + wn * 32 + nf * 8 + 2 * (lane & 3);
            #pragma unroll
            for (int u = 0; u < 2; u++)
                #pragma unroll
                for (int j = 0; j < 3; j++)
                    w3r[nf][u][j] = W3[(size_t)t * (HID * 3) + (nc + u) * 3 + j];
        }
    }

    float acc[2][4][4];
    #pragma unroll
    for (int i = 0; i < 2; i++)
        #pragma unroll
        for (int j = 0; j < 4; j++)
            #pragma unroll
            for (int k = 0; k < 4; k++) acc[i][j][k] = 0.0f;

    // per-lane ldmatrix addressing (SW128: xor (row&7)*16 within the 128B row)
    int aRow = lane & 15;
    int aKext = (lane >> 4) * 16;
    int bRow = ((lane >> 4) << 3) + (lane & 7);
    int bKext = ((lane >> 3) & 1) * 16;
    uint32_t xr = (uint32_t)((lane & 7) * 16);
    uint32_t aBase[2], bBase[2];
    #pragma unroll
    for (int mf = 0; mf < 2; mf++) aBase[mf] = (uint32_t)((wm * 32 + mf * 16 + aRow) * 128);
    #pragma unroll
    for (int n2 = 0; n2 < 2; n2++) bBase[n2] = (uint32_t)((wn * 32 + n2 * 16 + bRow) * 128);

    // chunk source pointers
    auto issue_stage = [&](int c, int buf) {
        const uint4 *Ah, *Al, *Bh, *Bl;
        if (MODE == 1) {
            Ah = g_fa_hi + (size_t)(mt * 3 + c) * 1024;
            Al = g_fa_lo + (size_t)(mt * 3 + c) * 1024;
            Bh = g_B1_hi + (size_t)(t * 3 + c) * 2048 + (size_t)by * 1024;
            Bl = g_B1_lo + (size_t)(t * 3 + c) * 2048 + (size_t)by * 1024;
        } else {
            Ah = g_h1_hi + (size_t)(mt * 4 + c) * 1024;
            Al = g_h1_lo + (size_t)(mt * 4 + c) * 1024;
            Bh = g_B2_hi + (size_t)(t * 4 + c) * 2048 + (size_t)by * 1024;
            Bl = g_B2_lo + (size_t)(t * 4 + c) * 2048 + (size_t)by * 1024;
        }
        uint32_t bb = s0 + buf * STAGE_BYTES;
        #pragma unroll
        for (int i = tid; i < 1024; i += 512) {
            cpa16(bb + i * 16,         Ah + i);
            cpa16(bb + 16384 + i * 16, Al + i);
            cpa16(bb + 32768 + i * 16, Bh + i);
            cpa16(bb + 49152 + i * 16, Bl + i);
        }
        CP_COMMIT();
    };

    issue_stage(0, 0);

    for (int c = 0; c < CHUNKS; c++) {
        if (c + 1 < CHUNKS) {
            issue_stage(c + 1, (c + 1) & 1);
            CP_WAIT1();
        } else {
            CP_WAIT0();
        }
        __syncthreads();

        uint32_t bb = s0 + (c & 1) * STAGE_BYTES;
        uint32_t sAh = bb, sAl = bb + 16384, sBh = bb + 32768, sBl = bb + 49152;

        #pragma unroll
        for (int k16 = 0; k16 < 4; k16++) {
            uint32_t kb = (uint32_t)(k16 * 32);
            uint32_t ah[2][4], al_[2][4], bh[2][4], bl[2][4];
            #pragma unroll
            for (int mf = 0; mf < 2; mf++) {
                uint32_t ka = (kb + (uint32_t)aKext) ^ xr;
                ldm_x4(ah[mf],  sAh + aBase[mf] + ka);
                ldm_x4(al_[mf], sAl + aBase[mf] + ka);
            }
            #pragma unroll
            for (int n2 = 0; n2 < 2; n2++) {
                uint32_t kbx = (kb + (uint32_t)bKext) ^ xr;
                ldm_x4(bh[n2], sBh + bBase[n2] + kbx);
                ldm_x4(bl[n2], sBl + bBase[n2] + kbx);
            }
            // pass 0: a_hi * b_hi
            #pragma unroll
            for (int mf = 0; mf < 2; mf++)
                #pragma unroll
                for (int nf = 0; nf < 4; nf++)
                    mma16816(acc[mf][nf], ah[mf], bh[nf >> 1][(nf & 1) * 2], bh[nf >> 1][(nf & 1) * 2 + 1]);
            // pass 1: a_lo * b_hi
            #pragma unroll
            for (int mf = 0; mf < 2; mf++)
                #pragma unroll
                for (int nf = 0; nf < 4; nf++)
                    mma16816(acc[mf][nf], al_[mf], bh[nf >> 1][(nf & 1) * 2], bh[nf >> 1][(nf & 1) * 2 + 1]);
            // pass 2: a_hi * b_lo
            #pragma unroll
            for (int mf = 0; mf < 2; mf++)
                #pragma unroll
                for (int nf = 0; nf < 4; nf++)
                    mma16816(acc[mf][nf], ah[mf], bl[nf >> 1][(nf & 1) * 2], bl[nf >> 1][(nf & 1) * 2 + 1]);
        }
        __syncthreads();
    }

    if (MODE == 1) {
        // relu + bf16 split, staged through smem (reuse stage 0), coalesced blob write
        #pragma unroll
        for (int mf = 0; mf < 2; mf++) {
            #pragma unroll
            for (int nf = 0; nf < 4; nf++) {
                int R0 = wm * 32 + mf * 16 + (lane >> 2);
                int nl = wn * 32 + nf * 8 + 2 * (lane & 3);
                int loc = nl >> 6, ncl = nl & 63;
                float c0 = fmaxf(acc[mf][nf][0], 0.0f);
                float c1 = fmaxf(acc[mf][nf][1], 0.0f);
                float c2 = fmaxf(acc[mf][nf][2], 0.0f);
                float c3 = fmaxf(acc[mf][nf][3], 0.0f);
                uint16_t h0, l0, h1, l1, h2, l2, h3, l3;
                bsplit(c0, h0, l0); bsplit(c1, h1, l1);
                bsplit(c2, h2, l2); bsplit(c3, h3, l3);
                uint32_t off0 = SW128((uint32_t)(R0 * 128 + ncl * 2));
                uint32_t off1 = SW128((uint32_t)((R0 + 8) * 128 + ncl * 2));
                uint32_t hbase = s0 + loc * 16384;
                uint32_t lbase = s0 + 32768 + loc * 16384;
                sts32(hbase + off0, pk16(h0, h1));
                sts32(hbase + off1, pk16(h2, h3));
                sts32(lbase + off0, pk16(l0, l1));
                sts32(lbase + off1, pk16(l2, l3));
            }
        }
        __syncthreads();
        const uint4* sh = (const uint4*)alp;
        const uint4* sl = (const uint4*)(alp + 32768);
        #pragma unroll
        for (int i = tid; i < 2048; i += 512) {
            int cg = by * 2 + (i >> 10);
            g_h1_hi[(size_t)(mt * 4 + cg) * 1024 + (i & 1023)] = sh[i];
            g_h1_lo[(size_t)(mt * 4 + cg) * 1024 + (i & 1023)] = sl[i];
        }
    } else {
        // relu + fused layer-3 dot + atomic scatter (out pre-zeroed)
        #pragma unroll
        for (int mf = 0; mf < 2; mf++) {
            float s0v[3] = {0.f, 0.f, 0.f}, s1v[3] = {0.f, 0.f, 0.f};
            #pragma unroll
            for (int nf = 0; nf < 4; nf++) {
                float h0 = fmaxf(acc[mf][nf][0], 0.0f);
                float h1 = fmaxf(acc[mf][nf][1], 0.0f);
                float h2 = fmaxf(acc[mf][nf][2], 0.0f);
                float h3 = fmaxf(acc[mf][nf][3], 0.0f);
                #pragma unroll
                for (int j = 0; j < 3; j++) {
                    s0v[j] += h0 * w3r[nf][0][j] + h1 * w3r[nf][1][j];
                    s1v[j] += h2 * w3r[nf][0][j] + h3 * w3r[nf][1][j];
                }
            }
            #pragma unroll
            for (int j = 0; j < 3; j++) {
                #pragma unroll
                for (int off = 1; off <= 2; off <<= 1) {
                    s0v[j] += __shfl_xor_sync(0xFFFFFFFFu, s0v[j], off);
                    s1v[j] += __shfl_xor_sync(0xFFFFFFFFu, s1v[j], off);
                }
            }
            if ((lane & 3) == 0) {
                int R0 = wm * 32 + mf * 16 + (lane >> 2);
                int g0 = m0 + R0, g1 = g0 + 8;
                if (g0 < Mt) {
                    int v = p.idx[t][g0];
                    #pragma unroll
                    for (int j = 0; j < 3; j++) atomicAdd(&out[(size_t)v * 3 + j], s0v[j]);
                }
                if (g1 < Mt) {
                    int v = p.idx[t][g1];
                    #pragma unroll
                    for (int j = 0; j < 3; j++) atomicAdd(&out[(size_t)v * 3 + j], s1v[j]);
                }
            }
        }
    }
}

// ---------------------------------------------------------------------------
// Launch
// ---------------------------------------------------------------------------
#define GEMM_SMEM (2 * STAGE_BYTES + 1024)

extern "C" void kernel_launch(void* const* d_in, const int* in_sizes, int n_in,
                              void* d_out, int out_size) {
    const float* imgs     = (const float*)d_in[0];
    const float* pros     = (const float*)d_in[1];
    const float* x_verts  = (const float*)d_in[2];
    const float* W1       = (const float*)d_in[3];
    const float* W2       = (const float*)d_in[4];
    const float* W3       = (const float*)d_in[5];
    const int*   imgbatch = (const int*)d_in[6];
    const int*   gov      = (const int*)d_in[7];
    float*       out      = (float*)d_out;

    P p;
    p.rowOff[0] = 0;
    p.tileOff[0] = 0;
    for (int t = 0; t < NTYPES; t++) {
        p.idx[t] = (const int*)d_in[8 + t];
        p.M[t] = in_sizes[8 + t];
        p.rowOff[t + 1] = p.rowOff[t] + p.M[t];
        p.tileOff[t + 1] = p.tileOff[t] + (p.M[t] + 127) / 128;
    }
    int tiles = p.tileOff[NTYPES];

    cudaFuncSetAttribute(gemm_mma_kernel<3, 1>, cudaFuncAttributeMaxDynamicSharedMemorySize, GEMM_SMEM);
    cudaFuncSetAttribute(gemm_mma_kernel<4, 2>, cudaFuncAttributeMaxDynamicSharedMemorySize, GEMM_SMEM);

    // zero the output (layer-3 scatter accumulates with atomics)
    cudaMemsetAsync(d_out, 0, (size_t)out_size * sizeof(float), 0);

    dim3 gG(GARM, CCH);
    roi_garf_kernel<<<gG, 256>>>(imgs, pros, imgbatch);

    dim3 gW(6, 7);
    wimg_kernel<<<gW, 256>>>(W1, W2);

    featimg_kernel<<<tiles, 128>>>(x_verts, gov, p);

    dim3 gM(2, tiles);
    gemm_mma_kernel<3, 1><<<gM, 512, GEMM_SMEM>>>(W3, out, p);
    gemm_mma_kernel<4, 2><<<gM, 512, GEMM_SMEM>>>(W3, out, p);
}

// round 5
// speedup vs baseline: 2.0736x; 1.1453x over previous
#include <cuda_runtime.h>
#include <cuda_bf16.h>
#include <cstdint>
#include <cstddef>

// ---------------------------------------------------------------------------
// Problem constants
// ---------------------------------------------------------------------------
#define NTYPES 6
#define HID    256
#define DV     128
#define CCH    64
#define IMH    192
#define IMW    192
#define GARM   24
#define MAXTILES 816   // sum ceil(M_t/128) <= 809; pad a little

// ---------------------------------------------------------------------------
// Static device scratch. Blob = the exact SMEM image a GEMM tile load wants:
//  A tile image: 128 rows x 64 bf16 (128B/row), SW128-swizzled -> 16KB = 1024 uint4
//  B tile image: 256 rows (n) x 64 bf16 (k)  -> 32KB = 2048 uint4   (B^T layout)
// ---------------------------------------------------------------------------
__device__ float g_garf[GARM * CCH];
__device__ uint4 g_fa_hi[(size_t)MAXTILES * 3 * 1024];
__device__ uint4 g_fa_lo[(size_t)MAXTILES * 3 * 1024];
__device__ uint4 g_h1_hi[(size_t)MAXTILES * 4 * 1024];
__device__ uint4 g_h1_lo[(size_t)MAXTILES * 4 * 1024];
__device__ uint4 g_B1_hi[6 * 3 * 2048];
__device__ uint4 g_B1_lo[6 * 3 * 2048];
__device__ uint4 g_B2_hi[6 * 4 * 2048];
__device__ uint4 g_B2_lo[6 * 4 * 2048];

struct P {
    const int* idx[NTYPES];
    int M[NTYPES];
    int rowOff[NTYPES + 1];
    int tileOff[NTYPES + 1];   // cumsum of ceil(M/128)
};

// ---------------------------------------------------------------------------
// Helpers (base-arch PTX only: ldmatrix / mma.sync / cp.async — all sm_80+)
// ---------------------------------------------------------------------------
__device__ __forceinline__ uint32_t smem_u32(const void* p) {
    uint32_t a;
    asm("{ .reg .u64 t; cvta.to.shared.u64 t, %1; cvt.u32.u64 %0, t; }" : "=r"(a) : "l"(p));
    return a;
}
#define SW128(x) ((x) ^ (((x) >> 3) & 0x70))

__device__ __forceinline__ void cpa16(uint32_t s, const void* g) {
    asm volatile("cp.async.cg.shared.global [%0], [%1], 16;" :: "r"(s), "l"(g));
}
#define CP_COMMIT() asm volatile("cp.async.commit_group;" ::: "memory")
#define CP_WAIT0()  asm volatile("cp.async.wait_group 0;" ::: "memory")
#define CP_WAIT1()  asm volatile("cp.async.wait_group 1;" ::: "memory")

__device__ __forceinline__ void ldm_x4(uint32_t* r, uint32_t addr) {
    asm volatile("ldmatrix.sync.aligned.m8n8.x4.shared.b16 {%0,%1,%2,%3}, [%4];"
                 : "=r"(r[0]), "=r"(r[1]), "=r"(r[2]), "=r"(r[3]) : "r"(addr));
}
__device__ __forceinline__ void mma16816(float* d, const uint32_t* a, uint32_t b0, uint32_t b1) {
    asm volatile(
        "mma.sync.aligned.m16n8k16.row.col.f32.bf16.bf16.f32 "
        "{%0,%1,%2,%3},{%4,%5,%6,%7},{%8,%9},{%0,%1,%2,%3};"
        : "+f"(d[0]), "+f"(d[1]), "+f"(d[2]), "+f"(d[3])
        : "r"(a[0]), "r"(a[1]), "r"(a[2]), "r"(a[3]), "r"(b0), "r"(b1));
}
__device__ __forceinline__ void sts32(uint32_t addr, uint32_t v) {
    asm volatile("st.shared.b32 [%0], %1;" :: "r"(addr), "r"(v) : "memory");
}

// bf16 hi/lo split + pack
__device__ __forceinline__ void bsplit(float x, uint16_t& h, uint16_t& l) {
    __nv_bfloat16 hb = __float2bfloat16_rn(x);
    float hf = __bfloat162float(hb);
    __nv_bfloat16 lb = __float2bfloat16_rn(x - hf);
    h = *reinterpret_cast<uint16_t*>(&hb);
    l = *reinterpret_cast<uint16_t*>(&lb);
}
__device__ __forceinline__ uint32_t pk16(uint16_t a, uint16_t b) {
    return (uint32_t)a | ((uint32_t)b << 16);
}
__device__ __forceinline__ void split8(const float* v, uint4& hq, uint4& lq) {
    uint16_t h[8], l[8];
    #pragma unroll
    for (int i = 0; i < 8; i++) bsplit(v[i], h[i], l[i]);
    hq = make_uint4(pk16(h[0], h[1]), pk16(h[2], h[3]), pk16(h[4], h[5]), pk16(h[6], h[7]));
    lq = make_uint4(pk16(l[0], l[1]), pk16(l[2], l[3]), pk16(l[4], l[5]), pk16(l[6], l[7]));
}

// ---------------------------------------------------------------------------
// Kernel 1: ROI-align + mean pool -> g_garf
// ---------------------------------------------------------------------------
__global__ void roi_garf_kernel(const float* __restrict__ imgs,
                                const float* __restrict__ pros,
                                const int* __restrict__ imgbatch) {
    int g = blockIdx.x, c = blockIdx.y, tid = threadIdx.x;
    int b = imgbatch[g];
    float px = pros[2 * g + 0], py = pros[2 * g + 1];
    const float* im = imgs + ((size_t)(b * CCH + c)) * (IMH * IMW);
    float sum = 0.0f;
    #pragma unroll
    for (int s = tid; s < 1024; s += 256) {
        int i = s >> 5, j = s & 31;
        float y = py - 16.0f + (float)i + 0.5f;
        float x = px - 16.0f + (float)j + 0.5f;
        float yf = floorf(y), xf = floorf(x);
        float wy = y - yf, wx = x - xf;
        int y0 = (int)yf, x0 = (int)xf, y1, x1;
        y1 = min(max(y0 + 1, 0), IMH - 1); x1 = min(max(x0 + 1, 0), IMW - 1);
        y0 = min(max(y0, 0), IMH - 1);     x0 = min(max(x0, 0), IMW - 1);
        float v00 = im[y0 * IMW + x0], v01 = im[y0 * IMW + x1];
        float v10 = im[y1 * IMW + x0], v11 = im[y1 * IMW + x1];
        sum += (1.0f - wy) * ((1.0f - wx) * v00 + wx * v01)
             +          wy * ((1.0f - wx) * v10 + wx * v11);
    }
    __shared__ float red[256];
    red[tid] = sum;
    __syncthreads();
    #pragma unroll
    for (int off = 128; off > 0; off >>= 1) {
        if (tid < off) red[tid] += red[tid + off];
        __syncthreads();
    }
    if (tid == 0) g_garf[g * CCH + c] = red[0] * (1.0f / 1024.0f);
}

// ---------------------------------------------------------------------------
// Kernel 2: weight images. grid (6, 7): y<3 -> layer1 chunk y, else layer2 y-3.
// ---------------------------------------------------------------------------
__global__ void wimg_kernel(const float* __restrict__ W1, const float* __restrict__ W2) {
    int t = blockIdx.x, cc = blockIdx.y, n = threadIdx.x;
    const float* W;
    uint4 *dh, *dl;
    int c;
    if (cc < 3) {
        c = cc;
        W = W1 + (size_t)t * 192 * 256;
        dh = g_B1_hi + (size_t)(t * 3 + c) * 2048;
        dl = g_B1_lo + (size_t)(t * 3 + c) * 2048;
    } else {
        c = cc - 3;
        W = W2 + (size_t)t * 256 * 256;
        dh = g_B2_hi + (size_t)(t * 4 + c) * 2048;
        dl = g_B2_lo + (size_t)(t * 4 + c) * 2048;
    }
    #pragma unroll
    for (int g4 = 0; g4 < 8; g4++) {
        float v[8];
        #pragma unroll
        for (int i = 0; i < 8; i++) v[i] = W[(size_t)(c * 64 + g4 * 8 + i) * 256 + n];
        uint4 hq, lq;
        split8(v, hq, lq);
        uint32_t sw = SW128((uint32_t)(n * 128 + g4 * 16));
        dh[sw >> 4] = hq;
        dl[sw >> 4] = lq;
    }
}

// ---------------------------------------------------------------------------
// Kernel 3: feature images. grid = tiles, 128 threads, one row each.
// ---------------------------------------------------------------------------
__global__ void featimg_kernel(const float* __restrict__ xv,
                               const int* __restrict__ gov, P p) {
    int mt = blockIdx.x, r = threadIdx.x;
    int t = 0;
    while (t < NTYPES - 1 && mt >= p.tileOff[t + 1]) t++;
    int grow = (mt - p.tileOff[t]) * 128 + r;
    bool valid = grow < p.M[t];
    int v = valid ? p.idx[t][grow] : 0;
    int g = valid ? gov[v] : 0;
    #pragma unroll
    for (int c = 0; c < 3; c++) {
        const float* src = (c < 2) ? (xv + (size_t)v * DV + c * 64) : (g_garf + g * CCH);
        uint4* dh = g_fa_hi + (size_t)(mt * 3 + c) * 1024;
        uint4* dl = g_fa_lo + (size_t)(mt * 3 + c) * 1024;
        #pragma unroll
        for (int g4 = 0; g4 < 8; g4++) {
            float v8[8];
            if (valid) {
                float4 f0 = *(const float4*)(src + g4 * 8);
                float4 f1 = *(const float4*)(src + g4 * 8 + 4);
                v8[0] = f0.x; v8[1] = f0.y; v8[2] = f0.z; v8[3] = f0.w;
                v8[4] = f1.x; v8[5] = f1.y; v8[6] = f1.z; v8[7] = f1.w;
            } else {
                #pragma unroll
                for (int i = 0; i < 8; i++) v8[i] = 0.0f;
            }
            uint4 hq, lq;
            split8(v8, hq, lq);
            uint32_t sw = SW128((uint32_t)(r * 128 + g4 * 16));
            dh[sw >> 4] = hq;
            dl[sw >> 4] = lq;
        }
    }
}

// ---------------------------------------------------------------------------
// Kernel 4/5: double-buffered mma.sync GEMM, 2 CTAs/SM.
// CTA = 64x128 output tile, 256 threads, 8 warps (2x4 grid of 32x32 tiles).
// grid = (2*tiles128 m-halves [fastest], 2 n-halves). 3-pass bf16 hi/lo.
// Stage = A(8+8KB) + B(16+16KB) = 48KB; 2 stages = 96KB -> 2 CTAs/SM.
// MODE 1: A = feat blobs (3 chunks), epilogue relu+split -> h1 blobs
// MODE 2: A = h1 blobs (4 chunks), epilogue relu + fused layer3 + atomic scatter
// ---------------------------------------------------------------------------
#define STAGE_BYTES 49152

template <int CHUNKS, int MODE>
__global__ __launch_bounds__(256, 2)
void gemm_mma_kernel(const float* __restrict__ W3, float* __restrict__ out, P p) {
    extern __shared__ char dsm[];
    int tid = threadIdx.x, lane = tid & 31, wid = tid >> 5;
    int wm = wid >> 2, wn = wid & 3;              // 2x4 warp grid, 32x32 tiles
    int bx = blockIdx.x, by = blockIdx.y;
    int mt = bx >> 1, rhalf = bx & 1;             // 128-row blob, 64-row half
    int t = 0;
    while (t < NTYPES - 1 && mt >= p.tileOff[t + 1]) t++;
    int m0 = (mt - p.tileOff[t]) * 128 + rhalf * 64;
    int Mt = p.M[t];

    uint32_t sbraw = smem_u32(dsm);
    uint32_t s0 = (sbraw + 1023u) & ~1023u;
    char* alp = dsm + (s0 - sbraw);

    // W3 columns owned by this thread (MODE 2 only)
    float w3r[4][2][3];
    if (MODE == 2) {
        #pragma unroll
        for (int nf = 0; nf < 4; nf++) {
            int nc = by * 128 + wn * 32 + nf * 8 + 2 * (lane & 3);
            #pragma unroll
            for (int u = 0; u < 2; u++)
                #pragma unroll
                for (int j = 0; j < 3; j++)
                    w3r[nf][u][j] = W3[(size_t)t * (HID * 3) + (nc + u) * 3 + j];
        }
    }

    float acc[2][4][4];
    #pragma unroll
    for (int i = 0; i < 2; i++)
        #pragma unroll
        for (int j = 0; j < 4; j++)
            #pragma unroll
            for (int k = 0; k < 4; k++) acc[i][j][k] = 0.0f;

    // per-lane ldmatrix addressing (SW128: xor (row&7)*16 within the 128B row)
    int aRow = lane & 15;
    int aKext = (lane >> 4) * 16;
    int bRow = ((lane >> 4) << 3) + (lane & 7);
    int bKext = ((lane >> 3) & 1) * 16;
    uint32_t xr = (uint32_t)((lane & 7) * 16);
    uint32_t aBase[2], bBase[2];
    #pragma unroll
    for (int mf = 0; mf < 2; mf++) aBase[mf] = (uint32_t)((wm * 32 + mf * 16 + aRow) * 128);
    #pragma unroll
    for (int n2 = 0; n2 < 2; n2++) bBase[n2] = (uint32_t)((wn * 32 + n2 * 16 + bRow) * 128);

    // stage layout: Ah @0 (8KB), Al @8192, Bh @16384 (16KB), Bl @32768 (16KB)
    auto issue_stage = [&](int c, int buf) {
        const uint4 *Ah, *Al, *Bh, *Bl;
        size_t aoff = (size_t)rhalf * 512;
        if (MODE == 1) {
            Ah = g_fa_hi + (size_t)(mt * 3 + c) * 1024 + aoff;
            Al = g_fa_lo + (size_t)(mt * 3 + c) * 1024 + aoff;
            Bh = g_B1_hi + (size_t)(t * 3 + c) * 2048 + (size_t)by * 1024;
            Bl = g_B1_lo + (size_t)(t * 3 + c) * 2048 + (size_t)by * 1024;
        } else {
            Ah = g_h1_hi + (size_t)(mt * 4 + c) * 1024 + aoff;
            Al = g_h1_lo + (size_t)(mt * 4 + c) * 1024 + aoff;
            Bh = g_B2_hi + (size_t)(t * 4 + c) * 2048 + (size_t)by * 1024;
            Bl = g_B2_lo + (size_t)(t * 4 + c) * 2048 + (size_t)by * 1024;
        }
        uint32_t bb = s0 + buf * STAGE_BYTES;
        #pragma unroll
        for (int i = tid; i < 512; i += 256) {
            cpa16(bb + i * 16,        Ah + i);
            cpa16(bb + 8192 + i * 16, Al + i);
        }
        #pragma unroll
        for (int i = tid; i < 1024; i += 256) {
            cpa16(bb + 16384 + i * 16, Bh + i);
            cpa16(bb + 32768 + i * 16, Bl + i);
        }
        CP_COMMIT();
    };

    issue_stage(0, 0);

    for (int c = 0; c < CHUNKS; c++) {
        if (c + 1 < CHUNKS) {
            issue_stage(c + 1, (c + 1) & 1);
            CP_WAIT1();
        } else {
            CP_WAIT0();
        }
        __syncthreads();

        uint32_t bb = s0 + (c & 1) * STAGE_BYTES;
        uint32_t sAh = bb, sAl = bb + 8192, sBh = bb + 16384, sBl = bb + 32768;

        #pragma unroll
        for (int k16 = 0; k16 < 4; k16++) {
            uint32_t kb = (uint32_t)(k16 * 32);
            uint32_t ah[2][4], al_[2][4], bh[2][4], bl[2][4];
            #pragma unroll
            for (int mf = 0; mf < 2; mf++) {
                uint32_t ka = (kb + (uint32_t)aKext) ^ xr;
                ldm_x4(ah[mf],  sAh + aBase[mf] + ka);
                ldm_x4(al_[mf], sAl + aBase[mf] + ka);
            }
            #pragma unroll
            for (int n2 = 0; n2 < 2; n2++) {
                uint32_t kbx = (kb + (uint32_t)bKext) ^ xr;
                ldm_x4(bh[n2], sBh + bBase[n2] + kbx);
                ldm_x4(bl[n2], sBl + bBase[n2] + kbx);
            }
            // pass 0: a_hi * b_hi
            #pragma unroll
            for (int mf = 0; mf < 2; mf++)
                #pragma unroll
                for (int nf = 0; nf < 4; nf++)
                    mma16816(acc[mf][nf], ah[mf], bh[nf >> 1][(nf & 1) * 2], bh[nf >> 1][(nf & 1) * 2 + 1]);
            // pass 1: a_lo * b_hi
            #pragma unroll
            for (int mf = 0; mf < 2; mf++)
                #pragma unroll
                for (int nf = 0; nf < 4; nf++)
                    mma16816(acc[mf][nf], al_[mf], bh[nf >> 1][(nf & 1) * 2], bh[nf >> 1][(nf & 1) * 2 + 1]);
            // pass 2: a_hi * b_lo
            #pragma unroll
            for (int mf = 0; mf < 2; mf++)
                #pragma unroll
                for (int nf = 0; nf < 4; nf++)
                    mma16816(acc[mf][nf], ah[mf], bl[nf >> 1][(nf & 1) * 2], bl[nf >> 1][(nf & 1) * 2 + 1]);
        }
        __syncthreads();
    }

    if (MODE == 1) {
        // relu + bf16 split, staged through smem (reuse stage0):
        //   hi: s0 + loc*8192 (64 rows x 128B), lo: s0 + 16384 + loc*8192
        #pragma unroll
        for (int mf = 0; mf < 2; mf++) {
            #pragma unroll
            for (int nf = 0; nf < 4; nf++) {
                int R0 = wm * 32 + mf * 16 + (lane >> 2);
                int nl = wn * 32 + nf * 8 + 2 * (lane & 3);
                int loc = nl >> 6, ncl = nl & 63;
                float c0 = fmaxf(acc[mf][nf][0], 0.0f);
                float c1 = fmaxf(acc[mf][nf][1], 0.0f);
                float c2 = fmaxf(acc[mf][nf][2], 0.0f);
                float c3 = fmaxf(acc[mf][nf][3], 0.0f);
                uint16_t h0, l0, h1, l1, h2, l2, h3, l3;
                bsplit(c0, h0, l0); bsplit(c1, h1, l1);
                bsplit(c2, h2, l2); bsplit(c3, h3, l3);
                uint32_t off0 = SW128((uint32_t)(R0 * 128 + ncl * 2));
                uint32_t off1 = SW128((uint32_t)((R0 + 8) * 128 + ncl * 2));
                uint32_t hbase = s0 + loc * 8192;
                uint32_t lbase = s0 + 16384 + loc * 8192;
                sts32(hbase + off0, pk16(h0, h1));
                sts32(hbase + off1, pk16(h2, h3));
                sts32(lbase + off0, pk16(l0, l1));
                sts32(lbase + off1, pk16(l2, l3));
            }
        }
        __syncthreads();
        const uint4* sh = (const uint4*)alp;
        const uint4* sl = (const uint4*)(alp + 16384);
        #pragma unroll
        for (int i = tid; i < 1024; i += 256) {
            int cg = by * 2 + (i >> 9);
            size_t bidx = (size_t)(mt * 4 + cg) * 1024 + (size_t)rhalf * 512 + (i & 511);
            g_h1_hi[bidx] = sh[i];
            g_h1_lo[bidx] = sl[i];
        }
    } else {
        // relu + fused layer-3 dot + atomic scatter (out pre-zeroed)
        #pragma unroll
        for (int mf = 0; mf < 2; mf++) {
            float s0v[3] = {0.f, 0.f, 0.f}, s1v[3] = {0.f, 0.f, 0.f};
            #pragma unroll
            for (int nf = 0; nf < 4; nf++) {
                float h0 = fmaxf(acc[mf][nf][0], 0.0f);
                float h1 = fmaxf(acc[mf][nf][1], 0.0f);
                float h2 = fmaxf(acc[mf][nf][2], 0.0f);
                float h3 = fmaxf(acc[mf][nf][3], 0.0f);
                #pragma unroll
                for (int j = 0; j < 3; j++) {
                    s0v[j] += h0 * w3r[nf][0][j] + h1 * w3r[nf][1][j];
                    s1v[j] += h2 * w3r[nf][0][j] + h3 * w3r[nf][1][j];
                }
            }
            #pragma unroll
            for (int j = 0; j < 3; j++) {
                #pragma unroll
                for (int off = 1; off <= 2; off <<= 1) {
                    s0v[j] += __shfl_xor_sync(0xFFFFFFFFu, s0v[j], off);
                    s1v[j] += __shfl_xor_sync(0xFFFFFFFFu, s1v[j], off);
                }
            }
            if ((lane & 3) == 0) {
                int R0 = wm * 32 + mf * 16 + (lane >> 2);
                int g0 = m0 + R0, g1 = g0 + 8;
                if (g0 < Mt) {
                    int v = p.idx[t][g0];
                    #pragma unroll
                    for (int j = 0; j < 3; j++) atomicAdd(&out[(size_t)v * 3 + j], s0v[j]);
                }
                if (g1 < Mt) {
                    int v = p.idx[t][g1];
                    #pragma unroll
                    for (int j = 0; j < 3; j++) atomicAdd(&out[(size_t)v * 3 + j], s1v[j]);
                }
            }
        }
    }
}

// ---------------------------------------------------------------------------
// Launch
// ---------------------------------------------------------------------------
#define GEMM_SMEM (2 * STAGE_BYTES + 1024)

extern "C" void kernel_launch(void* const* d_in, const int* in_sizes, int n_in,
                              void* d_out, int out_size) {
    const float* imgs     = (const float*)d_in[0];
    const float* pros     = (const float*)d_in[1];
    const float* x_verts  = (const float*)d_in[2];
    const float* W1       = (const float*)d_in[3];
    const float* W2       = (const float*)d_in[4];
    const float* W3       = (const float*)d_in[5];
    const int*   imgbatch = (const int*)d_in[6];
    const int*   gov      = (const int*)d_in[7];
    float*       out      = (float*)d_out;

    P p;
    p.rowOff[0] = 0;
    p.tileOff[0] = 0;
    for (int t = 0; t < NTYPES; t++) {
        p.idx[t] = (const int*)d_in[8 + t];
        p.M[t] = in_sizes[8 + t];
        p.rowOff[t + 1] = p.rowOff[t] + p.M[t];
        p.tileOff[t + 1] = p.tileOff[t] + (p.M[t] + 127) / 128;
    }
    int tiles = p.tileOff[NTYPES];

    cudaFuncSetAttribute(gemm_mma_kernel<3, 1>, cudaFuncAttributeMaxDynamicSharedMemorySize, GEMM_SMEM);
    cudaFuncSetAttribute(gemm_mma_kernel<4, 2>, cudaFuncAttributeMaxDynamicSharedMemorySize, GEMM_SMEM);

    // zero the output (layer-3 scatter accumulates with atomics)
    cudaMemsetAsync(d_out, 0, (size_t)out_size * sizeof(float), 0);

    dim3 gG(GARM, CCH);
    roi_garf_kernel<<<gG, 256>>>(imgs, pros, imgbatch);

    dim3 gW(6, 7);
    wimg_kernel<<<gW, 256>>>(W1, W2);

    featimg_kernel<<<tiles, 128>>>(x_verts, gov, p);

    dim3 gM(2 * tiles, 2);
    gemm_mma_kernel<3, 1><<<gM, 256, GEMM_SMEM>>>(W3, out, p);
    gemm_mma_kernel<4, 2><<<gM, 256, GEMM_SMEM>>>(W3, out, p);
}

// round 6
// speedup vs baseline: 2.2476x; 1.0839x over previous
#include <cuda_runtime.h>
#include <cuda_bf16.h>
#include <cstdint>
#include <cstddef>

// ---------------------------------------------------------------------------
// Problem constants
// ---------------------------------------------------------------------------
#define NTYPES 6
#define HID    256
#define DV     128
#define CCH    64
#define IMH    192
#define IMW    192
#define GARM   24
#define MAXTILES 816   // sum ceil(M_t/128) <= 809; pad a little

// ---------------------------------------------------------------------------
// Static device scratch. Blob = the exact SMEM image a GEMM tile load wants:
//  A tile image: 128 rows x 64 bf16 (128B/row), SW128-swizzled -> 16KB = 1024 uint4
//  B tile image: 256 rows (n) x 64 bf16 (k)  -> 32KB = 2048 uint4   (B^T layout)
// ---------------------------------------------------------------------------
__device__ float g_garf[GARM * CCH];
__device__ float g_bias[GARM * HID];                       // garf @ W1[128:192]
__device__ uint4 g_fa_hi[(size_t)MAXTILES * 2 * 1024];     // x_verts only (K=128)
__device__ uint4 g_fa_lo[(size_t)MAXTILES * 2 * 1024];
__device__ uint4 g_h1_hi[(size_t)MAXTILES * 4 * 1024];
__device__ uint4 g_h1_lo[(size_t)MAXTILES * 4 * 1024];
__device__ uint4 g_B1_hi[6 * 2 * 2048];                    // W1[:128] only
__device__ uint4 g_B1_lo[6 * 2 * 2048];
__device__ uint4 g_B2_hi[6 * 4 * 2048];
__device__ uint4 g_B2_lo[6 * 4 * 2048];

struct P {
    const int* idx[NTYPES];
    int M[NTYPES];
    int rowOff[NTYPES + 1];
    int tileOff[NTYPES + 1];   // cumsum of ceil(M/128)
};

// ---------------------------------------------------------------------------
// Helpers (base-arch PTX only: ldmatrix / mma.sync / cp.async — all sm_80+)
// ---------------------------------------------------------------------------
__device__ __forceinline__ uint32_t smem_u32(const void* p) {
    uint32_t a;
    asm("{ .reg .u64 t; cvta.to.shared.u64 t, %1; cvt.u32.u64 %0, t; }" : "=r"(a) : "l"(p));
    return a;
}
#define SW128(x) ((x) ^ (((x) >> 3) & 0x70))

__device__ __forceinline__ void cpa16(uint32_t s, const void* g) {
    asm volatile("cp.async.cg.shared.global [%0], [%1], 16;" :: "r"(s), "l"(g));
}
#define CP_COMMIT() asm volatile("cp.async.commit_group;" ::: "memory")
#define CP_WAIT0()  asm volatile("cp.async.wait_group 0;" ::: "memory")
#define CP_WAIT1()  asm volatile("cp.async.wait_group 1;" ::: "memory")

__device__ __forceinline__ void ldm_x4(uint32_t* r, uint32_t addr) {
    asm volatile("ldmatrix.sync.aligned.m8n8.x4.shared.b16 {%0,%1,%2,%3}, [%4];"
                 : "=r"(r[0]), "=r"(r[1]), "=r"(r[2]), "=r"(r[3]) : "r"(addr));
}
__device__ __forceinline__ void mma16816(float* d, const uint32_t* a, uint32_t b0, uint32_t b1) {
    asm volatile(
        "mma.sync.aligned.m16n8k16.row.col.f32.bf16.bf16.f32 "
        "{%0,%1,%2,%3},{%4,%5,%6,%7},{%8,%9},{%0,%1,%2,%3};"
        : "+f"(d[0]), "+f"(d[1]), "+f"(d[2]), "+f"(d[3])
        : "r"(a[0]), "r"(a[1]), "r"(a[2]), "r"(a[3]), "r"(b0), "r"(b1));
}
__device__ __forceinline__ void sts32(uint32_t addr, uint32_t v) {
    asm volatile("st.shared.b32 [%0], %1;" :: "r"(addr), "r"(v) : "memory");
}

// bf16 hi/lo split + pack
__device__ __forceinline__ void bsplit(float x, uint16_t& h, uint16_t& l) {
    __nv_bfloat16 hb = __float2bfloat16_rn(x);
    float hf = __bfloat162float(hb);
    __nv_bfloat16 lb = __float2bfloat16_rn(x - hf);
    h = *reinterpret_cast<uint16_t*>(&hb);
    l = *reinterpret_cast<uint16_t*>(&lb);
}
__device__ __forceinline__ uint32_t pk16(uint16_t a, uint16_t b) {
    return (uint32_t)a | ((uint32_t)b << 16);
}
__device__ __forceinline__ void split8(const float* v, uint4& hq, uint4& lq) {
    uint16_t h[8], l[8];
    #pragma unroll
    for (int i = 0; i < 8; i++) bsplit(v[i], h[i], l[i]);
    hq = make_uint4(pk16(h[0], h[1]), pk16(h[2], h[3]), pk16(h[4], h[5]), pk16(h[6], h[7]));
    lq = make_uint4(pk16(l[0], l[1]), pk16(l[2], l[3]), pk16(l[4], l[5]), pk16(l[6], l[7]));
}

// ---------------------------------------------------------------------------
// Kernel 1: ROI-align + mean pool -> g_garf
// ---------------------------------------------------------------------------
__global__ void roi_garf_kernel(const float* __restrict__ imgs,
                                const float* __restrict__ pros,
                                const int* __restrict__ imgbatch) {
    int g = blockIdx.x, c = blockIdx.y, tid = threadIdx.x;
    int b = imgbatch[g];
    float px = pros[2 * g + 0], py = pros[2 * g + 1];
    const float* im = imgs + ((size_t)(b * CCH + c)) * (IMH * IMW);
    float sum = 0.0f;
    #pragma unroll
    for (int s = tid; s < 1024; s += 256) {
        int i = s >> 5, j = s & 31;
        float y = py - 16.0f + (float)i + 0.5f;
        float x = px - 16.0f + (float)j + 0.5f;
        float yf = floorf(y), xf = floorf(x);
        float wy = y - yf, wx = x - xf;
        int y0 = (int)yf, x0 = (int)xf, y1, x1;
        y1 = min(max(y0 + 1, 0), IMH - 1); x1 = min(max(x0 + 1, 0), IMW - 1);
        y0 = min(max(y0, 0), IMH - 1);     x0 = min(max(x0, 0), IMW - 1);
        float v00 = im[y0 * IMW + x0], v01 = im[y0 * IMW + x1];
        float v10 = im[y1 * IMW + x0], v11 = im[y1 * IMW + x1];
        sum += (1.0f - wy) * ((1.0f - wx) * v00 + wx * v01)
             +          wy * ((1.0f - wx) * v10 + wx * v11);
    }
    __shared__ float red[256];
    red[tid] = sum;
    __syncthreads();
    #pragma unroll
    for (int off = 128; off > 0; off >>= 1) {
        if (tid < off) red[tid] += red[tid + off];
        __syncthreads();
    }
    if (tid == 0) g_garf[g * CCH + c] = red[0] * (1.0f / 1024.0f);
}

// ---------------------------------------------------------------------------
// Kernel 1b: per-garment layer-1 bias: bias[g] = garf[g] @ W1[t(g)][128:192].
// grid (6, 4): type t, garment slot j. 256 threads = one output col each.
// t(g) recovered from gov[idx_t[t][j * M_t/4]].
// ---------------------------------------------------------------------------
__global__ void bias_kernel(const float* __restrict__ W1,
                            const int* __restrict__ gov, P p) {
    int t = blockIdx.x, j = blockIdx.y, n = threadIdx.x;
    int g = gov[p.idx[t][j * (p.M[t] >> 2)]];
    const float* w = W1 + ((size_t)t * 192 + DV) * HID + n;   // rows 128..191, col n
    __shared__ float gf[CCH];
    if (n < CCH) gf[n] = g_garf[g * CCH + n];
    __syncthreads();
    float s = 0.0f;
    #pragma unroll 8
    for (int k = 0; k < CCH; k++) s += gf[k] * w[(size_t)k * HID];
    g_bias[g * HID + n] = s;
}

// ---------------------------------------------------------------------------
// Kernel 2: weight images. grid (6, 6): y<2 -> layer1 chunk y, else layer2 y-2.
// ---------------------------------------------------------------------------
__global__ void wimg_kernel(const float* __restrict__ W1, const float* __restrict__ W2) {
    int t = blockIdx.x, cc = blockIdx.y, n = threadIdx.x;
    const float* W;
    uint4 *dh, *dl;
    int c;
    if (cc < 2) {
        c = cc;
        W = W1 + (size_t)t * 192 * 256;
        dh = g_B1_hi + (size_t)(t * 2 + c) * 2048;
        dl = g_B1_lo + (size_t)(t * 2 + c) * 2048;
    } else {
        c = cc - 2;
        W = W2 + (size_t)t * 256 * 256;
        dh = g_B2_hi + (size_t)(t * 4 + c) * 2048;
        dl = g_B2_lo + (size_t)(t * 4 + c) * 2048;
    }
    #pragma unroll
    for (int g4 = 0; g4 < 8; g4++) {
        float v[8];
        #pragma unroll
        for (int i = 0; i < 8; i++) v[i] = W[(size_t)(c * 64 + g4 * 8 + i) * 256 + n];
        uint4 hq, lq;
        split8(v, hq, lq);
        uint32_t sw = SW128((uint32_t)(n * 128 + g4 * 16));
        dh[sw >> 4] = hq;
        dl[sw >> 4] = lq;
    }
}

// ---------------------------------------------------------------------------
// Kernel 3: feature images (x_verts only now). grid = tiles, 128 threads.
// ---------------------------------------------------------------------------
__global__ void featimg_kernel(const float* __restrict__ xv, P p) {
    int mt = blockIdx.x, r = threadIdx.x;
    int t = 0;
    while (t < NTYPES - 1 && mt >= p.tileOff[t + 1]) t++;
    int grow = (mt - p.tileOff[t]) * 128 + r;
    bool valid = grow < p.M[t];
    int v = valid ? p.idx[t][grow] : 0;
    #pragma unroll
    for (int c = 0; c < 2; c++) {
        const float* src = xv + (size_t)v * DV + c * 64;
        uint4* dh = g_fa_hi + (size_t)(mt * 2 + c) * 1024;
        uint4* dl = g_fa_lo + (size_t)(mt * 2 + c) * 1024;
        #pragma unroll
        for (int g4 = 0; g4 < 8; g4++) {
            float v8[8];
            if (valid) {
                float4 f0 = *(const float4*)(src + g4 * 8);
                float4 f1 = *(const float4*)(src + g4 * 8 + 4);
                v8[0] = f0.x; v8[1] = f0.y; v8[2] = f0.z; v8[3] = f0.w;
                v8[4] = f1.x; v8[5] = f1.y; v8[6] = f1.z; v8[7] = f1.w;
            } else {
                #pragma unroll
                for (int i = 0; i < 8; i++) v8[i] = 0.0f;
            }
            uint4 hq, lq;
            split8(v8, hq, lq);
            uint32_t sw = SW128((uint32_t)(r * 128 + g4 * 16));
            dh[sw >> 4] = hq;
            dl[sw >> 4] = lq;
        }
    }
}

// ---------------------------------------------------------------------------
// Kernel 4/5: double-buffered mma.sync GEMM, 2 CTAs/SM.
// CTA = 64x128 output tile, 256 threads, 8 warps (2x4 grid of 32x32 tiles).
// grid = (2*tiles128 m-halves [fastest], 2 n-halves). 3-pass bf16 hi/lo.
// MODE 1: A = feat blobs (2 chunks, K=128), acc init = per-garment bias,
//         epilogue relu+split -> h1 blobs.
// MODE 2: A = h1 blobs (4 chunks), epilogue relu + fused layer3 + atomic scatter.
// ---------------------------------------------------------------------------
#define STAGE_BYTES 49152

template <int CHUNKS, int MODE>
__global__ __launch_bounds__(256, 2)
void gemm_mma_kernel(const float* __restrict__ W3,
                     const int* __restrict__ gov,
                     float* __restrict__ out, P p) {
    extern __shared__ char dsm[];
    int tid = threadIdx.x, lane = tid & 31, wid = tid >> 5;
    int wm = wid >> 2, wn = wid & 3;              // 2x4 warp grid, 32x32 tiles
    int bx = blockIdx.x, by = blockIdx.y;
    int mt = bx >> 1, rhalf = bx & 1;             // 128-row blob, 64-row half
    int t = 0;
    while (t < NTYPES - 1 && mt >= p.tileOff[t + 1]) t++;
    int m0 = (mt - p.tileOff[t]) * 128 + rhalf * 64;
    int Mt = p.M[t];

    uint32_t sbraw = smem_u32(dsm);
    uint32_t s0 = (sbraw + 1023u) & ~1023u;
    char* alp = dsm + (s0 - sbraw);

    // W3 columns owned by this thread (MODE 2 only)
    float w3r[4][2][3];
    if (MODE == 2) {
        #pragma unroll
        for (int nf = 0; nf < 4; nf++) {
            int nc = by * 128 + wn * 32 + nf * 8 + 2 * (lane & 3);
            #pragma unroll
            for (int u = 0; u < 2; u++)
                #pragma unroll
                for (int j = 0; j < 3; j++)
                    w3r[nf][u][j] = W3[(size_t)t * (HID * 3) + (nc + u) * 3 + j];
        }
    }

    float acc[2][4][4];
    if (MODE == 1) {
        // accumulator init = per-garment bias (garf @ W1[128:192])
        #pragma unroll
        for (int mf = 0; mf < 2; mf++) {
            int r0 = m0 + wm * 32 + mf * 16 + (lane >> 2);
            int r1 = r0 + 8;
            int v0 = p.idx[t][min(r0, Mt - 1)];
            int v1 = p.idx[t][min(r1, Mt - 1)];
            int g0 = gov[v0], g1 = gov[v1];
            #pragma unroll
            for (int nf = 0; nf < 4; nf++) {
                int nl = by * 128 + wn * 32 + nf * 8 + 2 * (lane & 3);
                acc[mf][nf][0] = g_bias[g0 * HID + nl];
                acc[mf][nf][1] = g_bias[g0 * HID + nl + 1];
                acc[mf][nf][2] = g_bias[g1 * HID + nl];
                acc[mf][nf][3] = g_bias[g1 * HID + nl + 1];
            }
        }
    } else {
        #pragma unroll
        for (int i = 0; i < 2; i++)
            #pragma unroll
            for (int j = 0; j < 4; j++)
                #pragma unroll
                for (int k = 0; k < 4; k++) acc[i][j][k] = 0.0f;
    }

    // per-lane ldmatrix addressing (SW128: xor (row&7)*16 within the 128B row)
    int aRow = lane & 15;
    int aKext = (lane >> 4) * 16;
    int bRow = ((lane >> 4) << 3) + (lane & 7);
    int bKext = ((lane >> 3) & 1) * 16;
    uint32_t xr = (uint32_t)((lane & 7) * 16);
    uint32_t aBase[2], bBase[2];
    #pragma unroll
    for (int mf = 0; mf < 2; mf++) aBase[mf] = (uint32_t)((wm * 32 + mf * 16 + aRow) * 128);
    #pragma unroll
    for (int n2 = 0; n2 < 2; n2++) bBase[n2] = (uint32_t)((wn * 32 + n2 * 16 + bRow) * 128);

    // stage layout: Ah @0 (8KB), Al @8192, Bh @16384 (16KB), Bl @32768 (16KB)
    auto issue_stage = [&](int c, int buf) {
        const uint4 *Ah, *Al, *Bh, *Bl;
        size_t aoff = (size_t)rhalf * 512;
        if (MODE == 1) {
            Ah = g_fa_hi + (size_t)(mt * 2 + c) * 1024 + aoff;
            Al = g_fa_lo + (size_t)(mt * 2 + c) * 1024 + aoff;
            Bh = g_B1_hi + (size_t)(t * 2 + c) * 2048 + (size_t)by * 1024;
            Bl = g_B1_lo + (size_t)(t * 2 + c) * 2048 + (size_t)by * 1024;
        } else {
            Ah = g_h1_hi + (size_t)(mt * 4 + c) * 1024 + aoff;
            Al = g_h1_lo + (size_t)(mt * 4 + c) * 1024 + aoff;
            Bh = g_B2_hi + (size_t)(t * 4 + c) * 2048 + (size_t)by * 1024;
            Bl = g_B2_lo + (size_t)(t * 4 + c) * 2048 + (size_t)by * 1024;
        }
        uint32_t bb = s0 + buf * STAGE_BYTES;
        #pragma unroll
        for (int i = tid; i < 512; i += 256) {
            cpa16(bb + i * 16,        Ah + i);
            cpa16(bb + 8192 + i * 16, Al + i);
        }
        #pragma unroll
        for (int i = tid; i < 1024; i += 256) {
            cpa16(bb + 16384 + i * 16, Bh + i);
            cpa16(bb + 32768 + i * 16, Bl + i);
        }
        CP_COMMIT();
    };

    issue_stage(0, 0);

    for (int c = 0; c < CHUNKS; c++) {
        if (c + 1 < CHUNKS) {
            issue_stage(c + 1, (c + 1) & 1);
            CP_WAIT1();
        } else {
            CP_WAIT0();
        }
        __syncthreads();

        uint32_t bb = s0 + (c & 1) * STAGE_BYTES;
        uint32_t sAh = bb, sAl = bb + 8192, sBh = bb + 16384, sBl = bb + 32768;

        #pragma unroll
        for (int k16 = 0; k16 < 4; k16++) {
            uint32_t kb = (uint32_t)(k16 * 32);
            uint32_t ah[2][4], al_[2][4], bh[2][4], bl[2][4];
            #pragma unroll
            for (int mf = 0; mf < 2; mf++) {
                uint32_t ka = (kb + (uint32_t)aKext) ^ xr;
                ldm_x4(ah[mf],  sAh + aBase[mf] + ka);
                ldm_x4(al_[mf], sAl + aBase[mf] + ka);
            }
            #pragma unroll
            for (int n2 = 0; n2 < 2; n2++) {
                uint32_t kbx = (kb + (uint32_t)bKext) ^ xr;
                ldm_x4(bh[n2], sBh + bBase[n2] + kbx);
                ldm_x4(bl[n2], sBl + bBase[n2] + kbx);
            }
            // pass 0: a_hi * b_hi
            #pragma unroll
            for (int mf = 0; mf < 2; mf++)
                #pragma unroll
                for (int nf = 0; nf < 4; nf++)
                    mma16816(acc[mf][nf], ah[mf], bh[nf >> 1][(nf & 1) * 2], bh[nf >> 1][(nf & 1) * 2 + 1]);
            // pass 1: a_lo * b_hi
            #pragma unroll
            for (int mf = 0; mf < 2; mf++)
                #pragma unroll
                for (int nf = 0; nf < 4; nf++)
                    mma16816(acc[mf][nf], al_[mf], bh[nf >> 1][(nf & 1) * 2], bh[nf >> 1][(nf & 1) * 2 + 1]);
            // pass 2: a_hi * b_lo
            #pragma unroll
            for (int mf = 0; mf < 2; mf++)
                #pragma unroll
                for (int nf = 0; nf < 4; nf++)
                    mma16816(acc[mf][nf], ah[mf], bl[nf >> 1][(nf & 1) * 2], bl[nf >> 1][(nf & 1) * 2 + 1]);
        }
        __syncthreads();
    }

    if (MODE == 1) {
        // relu + bf16 split, staged through smem (reuse stage0):
        //   hi: s0 + loc*8192 (64 rows x 128B), lo: s0 + 16384 + loc*8192
        #pragma unroll
        for (int mf = 0; mf < 2; mf++) {
            #pragma unroll
            for (int nf = 0; nf < 4; nf++) {
                int R0 = wm * 32 + mf * 16 + (lane >> 2);
                int nl = wn * 32 + nf * 8 + 2 * (lane & 3);
                int loc = nl >> 6, ncl = nl & 63;
                float c0 = fmaxf(acc[mf][nf][0], 0.0f);
                float c1 = fmaxf(acc[mf][nf][1], 0.0f);
                float c2 = fmaxf(acc[mf][nf][2], 0.0f);
                float c3 = fmaxf(acc[mf][nf][3], 0.0f);
                uint16_t h0, l0, h1, l1, h2, l2, h3, l3;
                bsplit(c0, h0, l0); bsplit(c1, h1, l1);
                bsplit(c2, h2, l2); bsplit(c3, h3, l3);
                uint32_t off0 = SW128((uint32_t)(R0 * 128 + ncl * 2));
                uint32_t off1 = SW128((uint32_t)((R0 + 8) * 128 + ncl * 2));
                uint32_t hbase = s0 + loc * 8192;
                uint32_t lbase = s0 + 16384 + loc * 8192;
                sts32(hbase + off0, pk16(h0, h1));
                sts32(hbase + off1, pk16(h2, h3));
                sts32(lbase + off0, pk16(l0, l1));
                sts32(lbase + off1, pk16(l2, l3));
            }
        }
        __syncthreads();
        const uint4* sh = (const uint4*)alp;
        const uint4* sl = (const uint4*)(alp + 16384);
        #pragma unroll
        for (int i = tid; i < 1024; i += 256) {
            int cg = by * 2 + (i >> 9);
            size_t bidx = (size_t)(mt * 4 + cg) * 1024 + (size_t)rhalf * 512 + (i & 511);
            g_h1_hi[bidx] = sh[i];
            g_h1_lo[bidx] = sl[i];
        }
    } else {
        // relu + fused layer-3 dot + atomic scatter (out pre-zeroed)
        #pragma unroll
        for (int mf = 0; mf < 2; mf++) {
            float s0v[3] = {0.f, 0.f, 0.f}, s1v[3] = {0.f, 0.f, 0.f};
            #pragma unroll
            for (int nf = 0; nf < 4; nf++) {
                float h0 = fmaxf(acc[mf][nf][0], 0.0f);
                float h1 = fmaxf(acc[mf][nf][1], 0.0f);
                float h2 = fmaxf(acc[mf][nf][2], 0.0f);
                float h3 = fmaxf(acc[mf][nf][3], 0.0f);
                #pragma unroll
                for (int j = 0; j < 3; j++) {
                    s0v[j] += h0 * w3r[nf][0][j] + h1 * w3r[nf][1][j];
                    s1v[j] += h2 * w3r[nf][0][j] + h3 * w3r[nf][1][j];
                }
            }
            #pragma unroll
            for (int j = 0; j < 3; j++) {
                #pragma unroll
                for (int off = 1; off <= 2; off <<= 1) {
                    s0v[j] += __shfl_xor_sync(0xFFFFFFFFu, s0v[j], off);
                    s1v[j] += __shfl_xor_sync(0xFFFFFFFFu, s1v[j], off);
                }
            }
            if ((lane & 3) == 0) {
                int R0 = wm * 32 + mf * 16 + (lane >> 2);
                int g0 = m0 + R0, g1 = g0 + 8;
                if (g0 < Mt) {
                    int v = p.idx[t][g0];
                    #pragma unroll
                    for (int j = 0; j < 3; j++) atomicAdd(&out[(size_t)v * 3 + j], s0v[j]);
                }
                if (g1 < Mt) {
                    int v = p.idx[t][g1];
                    #pragma unroll
                    for (int j = 0; j < 3; j++) atomicAdd(&out[(size_t)v * 3 + j], s1v[j]);
                }
            }
        }
    }
}

// ---------------------------------------------------------------------------
// Launch
// ---------------------------------------------------------------------------
#define GEMM_SMEM (2 * STAGE_BYTES + 1024)

extern "C" void kernel_launch(void* const* d_in, const int* in_sizes, int n_in,
                              void* d_out, int out_size) {
    const float* imgs     = (const float*)d_in[0];
    const float* pros     = (const float*)d_in[1];
    const float* x_verts  = (const float*)d_in[2];
    const float* W1       = (const float*)d_in[3];
    const float* W2       = (const float*)d_in[4];
    const float* W3       = (const float*)d_in[5];
    const int*   imgbatch = (const int*)d_in[6];
    const int*   gov      = (const int*)d_in[7];
    float*       out      = (float*)d_out;

    P p;
    p.rowOff[0] = 0;
    p.tileOff[0] = 0;
    for (int t = 0; t < NTYPES; t++) {
        p.idx[t] = (const int*)d_in[8 + t];
        p.M[t] = in_sizes[8 + t];
        p.rowOff[t + 1] = p.rowOff[t] + p.M[t];
        p.tileOff[t + 1] = p.tileOff[t] + (p.M[t] + 127) / 128;
    }
    int tiles = p.tileOff[NTYPES];

    cudaFuncSetAttribute(gemm_mma_kernel<2, 1>, cudaFuncAttributeMaxDynamicSharedMemorySize, GEMM_SMEM);
    cudaFuncSetAttribute(gemm_mma_kernel<4, 2>, cudaFuncAttributeMaxDynamicSharedMemorySize, GEMM_SMEM);

    // zero the output (layer-3 scatter accumulates with atomics)
    cudaMemsetAsync(d_out, 0, (size_t)out_size * sizeof(float), 0);

    dim3 gG(GARM, CCH);
    roi_garf_kernel<<<gG, 256>>>(imgs, pros, imgbatch);

    dim3 gW(6, 6);
    wimg_kernel<<<gW, 256>>>(W1, W2);

    featimg_kernel<<<tiles, 128>>>(x_verts, p);

    dim3 gB(6, 4);
    bias_kernel<<<gB, 256>>>(W1, gov, p);

    dim3 gM(2 * tiles, 2);
    gemm_mma_kernel<2, 1><<<gM, 256, GEMM_SMEM>>>(W3, gov, out, p);
    gemm_mma_kernel<4, 2><<<gM, 256, GEMM_SMEM>>>(W3, gov, out, p);
}